// round 13
// baseline (speedup 1.0000x reference)
#include <cuda_runtime.h>
#include <cuda_bf16.h>
#include <cstdint>
#include <math.h>

#define NN 4096

// ---------------- scratch (device globals) ----------------
__device__ __nv_bfloat16 g_Phi[(size_t)NN * NN];   // single P slot (hi) - L2 resident
__device__ __nv_bfloat16 g_Plo[(size_t)NN * NN];   // single P slot (lo)
__device__ float g_hA[NN * 512];
__device__ __nv_bfloat16 g_hAhi[NN * 512];
__device__ __nv_bfloat16 g_hAlo[NN * 512];
__device__ float g_out1[NN * 512];
__device__ __nv_bfloat16 g_out1hi[NN * 512];
__device__ __nv_bfloat16 g_out1lo[NN * 512];
__device__ float g_cat[NN * 1536];
__device__ __nv_bfloat16 g_cathi[NN * 1536];
__device__ __nv_bfloat16 g_catlo[NN * 1536];
__device__ float g_hB6[6 * NN * 256];
__device__ __nv_bfloat16 g_hB6hi[6 * NN * 256];
__device__ __nv_bfloat16 g_hB6lo[6 * NN * 256];
__device__ float g_hB[NN * 256];
__device__ __nv_bfloat16 g_hBhi[NN * 256];
__device__ __nv_bfloat16 g_hBlo[NN * 256];
__device__ __nv_bfloat16 g_attWhi[6 * 512 * 256];
__device__ __nv_bfloat16 g_attWlo[6 * 512 * 256];
__device__ __nv_bfloat16 g_c2Whi[1536 * 256];
__device__ __nv_bfloat16 g_c2Wlo[1536 * 256];
__device__ float g_l1[NN * 64];
__device__ float g_l2[NN * 64];
__device__ float g_sv[8 * NN];
__device__ float g_tv[8 * NN];
__device__ float g_E[8 * NN];
__device__ float g_Fv[8 * NN];
__device__ unsigned g_maxtKey[8];
__device__ float g_maxt[8];
__device__ float g_invZ[8 * NN];
__device__ unsigned g_mask[NN * 128];
__device__ float g_part[2 * 2048];
__device__ float g_stats[2];

__device__ __forceinline__ unsigned fenc(float f) {
    unsigned u = __float_as_uint(f);
    return (u & 0x80000000u) ? ~u : (u | 0x80000000u);
}
__device__ __forceinline__ float fdec(unsigned k) {
    unsigned u = (k & 0x80000000u) ? (k & 0x7fffffffu) : ~k;
    return __uint_as_float(u);
}
__device__ __forceinline__ unsigned sptr(const void* p) {
    return (unsigned)__cvta_generic_to_shared(p);
}
__device__ __forceinline__ void cpasync16(unsigned s, const void* g) {
    asm volatile("cp.async.cg.shared.global [%0], [%1], 16;\n" :: "r"(s), "l"(g));
}
__device__ __forceinline__ void ldm_x4(unsigned a, unsigned& r0, unsigned& r1,
                                       unsigned& r2, unsigned& r3) {
    asm volatile("ldmatrix.sync.aligned.m8n8.x4.shared.b16 {%0,%1,%2,%3}, [%4];"
                 : "=r"(r0), "=r"(r1), "=r"(r2), "=r"(r3) : "r"(a));
}
__device__ __forceinline__ void ldm_x4t(unsigned a, unsigned& r0, unsigned& r1,
                                        unsigned& r2, unsigned& r3) {
    asm volatile("ldmatrix.sync.aligned.m8n8.x4.trans.shared.b16 {%0,%1,%2,%3}, [%4];"
                 : "=r"(r0), "=r"(r1), "=r"(r2), "=r"(r3) : "r"(a));
}
__device__ __forceinline__ void mma16816(float* c, const unsigned* a, const unsigned* b) {
    asm volatile(
        "mma.sync.aligned.m16n8k16.row.col.f32.bf16.bf16.f32 "
        "{%0,%1,%2,%3},{%4,%5,%6,%7},{%8,%9},{%0,%1,%2,%3};"
        : "+f"(c[0]), "+f"(c[1]), "+f"(c[2]), "+f"(c[3])
        : "r"(a[0]), "r"(a[1]), "r"(a[2]), "r"(a[3]), "r"(b[0]), "r"(b[1]));
}
__device__ __forceinline__ void split1(float v, __nv_bfloat16& hi, __nv_bfloat16& lo) {
    hi = __float2bfloat16(v);
    lo = __float2bfloat16(v - __bfloat162float(hi));
}

// ---------------- bitmask pack + maxt reset ----------------
__global__ void pack_mask_k(const int* __restrict__ adj, unsigned* __restrict__ mask,
                            unsigned* __restrict__ keys) {
    int i = blockIdx.x;
    int w = threadIdx.x;
    if (i == 0 && w < 8) keys[w] = 0u;
    const int* row = adj + (size_t)i * NN + w * 32;
    unsigned bits = 0;
#pragma unroll
    for (int b = 0; b < 32; b++) bits |= (row[b] > 0 ? 1u : 0u) << b;
    mask[i * 128 + w] = bits;
}

// ---------------- fp32 GEMM for the small projections ----------------
template <int BN, int TN>
__global__ void __launch_bounds__(256) gemm128_k(
    const float* __restrict__ A, const float* __restrict__ B, float* __restrict__ C,
    int K, int lda, int ldb, int ldc,
    const float* __restrict__ bias, int act) {
    __shared__ float As[2][16][128];
    __shared__ float Bs[2][16][BN];
    const int tid = threadIdx.x;
    const int tx = tid & 15, ty = tid >> 4;
    const int row0 = blockIdx.y * 128, col0 = blockIdx.x * BN;
    int am[2], akq[2];
#pragma unroll
    for (int i = 0; i < 2; i++) {
        int idx = tid + i * 256;
        am[i] = idx >> 2;
        akq[i] = (idx & 3) << 2;
    }
    constexpr int BCNT = (16 * BN / 4) / 256;
    int bk[BCNT], bn[BCNT];
#pragma unroll
    for (int i = 0; i < BCNT; i++) {
        int idx = tid + i * 256;
        bk[i] = idx / (BN / 4);
        bn[i] = (idx % (BN / 4)) << 2;
    }
    float acc[8][TN];
#pragma unroll
    for (int i = 0; i < 8; i++)
#pragma unroll
        for (int j = 0; j < TN; j++) acc[i][j] = 0.f;
    float4 aR[2];
    float4 bR[BCNT];
#pragma unroll
    for (int i = 0; i < 2; i++)
        aR[i] = *(const float4*)(A + (size_t)(row0 + am[i]) * lda + akq[i]);
#pragma unroll
    for (int i = 0; i < BCNT; i++)
        bR[i] = *(const float4*)(B + (size_t)bk[i] * ldb + col0 + bn[i]);
#pragma unroll
    for (int i = 0; i < 2; i++) {
        As[0][akq[i] + 0][am[i]] = aR[i].x;
        As[0][akq[i] + 1][am[i]] = aR[i].y;
        As[0][akq[i] + 2][am[i]] = aR[i].z;
        As[0][akq[i] + 3][am[i]] = aR[i].w;
    }
#pragma unroll
    for (int i = 0; i < BCNT; i++) *(float4*)&Bs[0][bk[i]][bn[i]] = bR[i];
    __syncthreads();
    const int nT = K >> 4;
    for (int t = 0; t < nT; t++) {
        const int buf = t & 1;
        if (t + 1 < nT) {
            const int k0 = (t + 1) << 4;
#pragma unroll
            for (int i = 0; i < 2; i++)
                aR[i] = *(const float4*)(A + (size_t)(row0 + am[i]) * lda + k0 + akq[i]);
#pragma unroll
            for (int i = 0; i < BCNT; i++)
                bR[i] = *(const float4*)(B + (size_t)(k0 + bk[i]) * ldb + col0 + bn[i]);
        }
#pragma unroll
        for (int kk = 0; kk < 16; kk++) {
            float4 a0 = *(const float4*)&As[buf][kk][ty * 8];
            float4 a1 = *(const float4*)&As[buf][kk][ty * 8 + 4];
            float av[8] = {a0.x, a0.y, a0.z, a0.w, a1.x, a1.y, a1.z, a1.w};
            float bv[TN];
            float4 b0 = *(const float4*)&Bs[buf][kk][tx * TN];
            bv[0] = b0.x; bv[1] = b0.y; bv[2] = b0.z; bv[3] = b0.w;
            if (TN == 8) {
                float4 b1 = *(const float4*)&Bs[buf][kk][tx * TN + 4];
                bv[4] = b1.x; bv[5] = b1.y; bv[6] = b1.z; bv[7] = b1.w;
            }
#pragma unroll
            for (int i = 0; i < 8; i++)
#pragma unroll
                for (int j = 0; j < TN; j++) acc[i][j] += av[i] * bv[j];
        }
        if (t + 1 < nT) {
            const int nb = buf ^ 1;
#pragma unroll
            for (int i = 0; i < 2; i++) {
                As[nb][akq[i] + 0][am[i]] = aR[i].x;
                As[nb][akq[i] + 1][am[i]] = aR[i].y;
                As[nb][akq[i] + 2][am[i]] = aR[i].z;
                As[nb][akq[i] + 3][am[i]] = aR[i].w;
            }
#pragma unroll
            for (int i = 0; i < BCNT; i++) *(float4*)&Bs[nb][bk[i]][bn[i]] = bR[i];
            __syncthreads();
        }
    }
#pragma unroll
    for (int i = 0; i < 8; i++) {
        int row = row0 + ty * 8 + i;
#pragma unroll
        for (int j4 = 0; j4 < TN; j4 += 4) {
            float r[4];
#pragma unroll
            for (int j = 0; j < 4; j++) {
                float x = acc[i][j4 + j];
                if (bias) x += bias[col0 + tx * TN + j4 + j];
                if (act == 1) x = fmaxf(x, 0.f);
                r[j] = x;
            }
            *(float4*)(C + (size_t)row * ldc + col0 + tx * TN + j4) =
                make_float4(r[0], r[1], r[2], r[3]);
        }
    }
}

// ---------------- 3xBF16 tensor-core GEMM, 4-stage pipeline, 2 CTAs/SM ----------------
template <int MT>
__global__ void __launch_bounds__(256, 2) mma3_k(
    const __nv_bfloat16* __restrict__ Ahi, const __nv_bfloat16* __restrict__ Alo,
    const __nv_bfloat16* __restrict__ Bhi, const __nv_bfloat16* __restrict__ Blo,
    float* __restrict__ C, __nv_bfloat16* __restrict__ Chi, __nv_bfloat16* __restrict__ Clo,
    int K, int lda, int ldb, int ldc,
    const float* __restrict__ rowScale, int act,
    long strideAz, long strideBz, long strideCz, int rsStride) {
    constexpr int BM = MT * 32;
    constexpr int ABYTES = BM * 128;
    constexpr int BBYTES = 32 * 512;
    constexpr int LA = BM / 32;

    extern __shared__ __align__(16) char smraw[];
    unsigned aBase = sptr(smraw);
    unsigned bBase = aBase + 4 * ABYTES;

    const int z = blockIdx.z;
    Ahi += (long)z * strideAz;
    Alo += (long)z * strideAz;
    Bhi += (long)z * strideBz;
    Blo += (long)z * strideBz;
    long cz = (long)z * strideCz;
    const int rs0 = z * rsStride;

    const int tid = threadIdx.x;
    const int w = tid >> 5, lane = tid & 31;
    const int wm = w >> 2, wn = w & 3;
    const int row0 = blockIdx.y * BM, col0 = blockIdx.x * 128;
    const int nT = K >> 5;

    auto loadTile = [&](int buf, int k0) {
#pragma unroll
        for (int i = 0; i < LA; i++) {
            int idx = i * 256 + tid;
            int plane = idx >= BM * 4 ? 1 : 0;
            int ii = idx - plane * BM * 4;
            int r = ii >> 2, c4 = ii & 3;
            const __nv_bfloat16* g =
                (plane ? Alo : Ahi) + (size_t)(row0 + r) * lda + k0 + c4 * 8;
            int c = c4 + plane * 4;
            cpasync16(aBase + buf * ABYTES + r * 128 + ((c ^ (r & 7)) << 4), g);
        }
#pragma unroll
        for (int i = 0; i < 4; i++) {
            int idx = i * 256 + tid;
            int plane = idx >> 9;
            int ii = idx & 511;
            int k = ii >> 4, c16 = ii & 15;
            const __nv_bfloat16* g =
                (plane ? Blo : Bhi) + (size_t)(k0 + k) * ldb + col0 + c16 * 8;
            int c = c16 + plane * 16;
            int p = (c & 24) | ((c ^ k) & 7);
            cpasync16(bBase + buf * BBYTES + k * 512 + (p << 4), g);
        }
    };

    float acc[MT][4][4];
#pragma unroll
    for (int m = 0; m < MT; m++)
#pragma unroll
        for (int n = 0; n < 4; n++)
#pragma unroll
            for (int q = 0; q < 4; q++) acc[m][n][q] = 0.f;

    loadTile(0, 0);
    asm volatile("cp.async.commit_group;\n" ::);
    loadTile(1, 32);
    asm volatile("cp.async.commit_group;\n" ::);
    loadTile(2, 64);
    asm volatile("cp.async.commit_group;\n" ::);

    for (int t = 0; t < nT; t++) {
        asm volatile("cp.async.wait_group 2;\n" ::);
        __syncthreads();
        if (t + 3 < nT) {
            loadTile((t + 3) & 3, (t + 3) * 32);
        }
        asm volatile("cp.async.commit_group;\n" ::);

        const int buf = t & 3;
#pragma unroll
        for (int ks = 0; ks < 2; ks++) {
            unsigned ah[MT][4], al[MT][4], bh[4][2], bl[4][2];
#pragma unroll
            for (int mt = 0; mt < MT; mt++) {
                int rA = wm * MT * 16 + mt * 16 + (lane & 15);
                int ck = ks * 2 + (lane >> 4);
                unsigned base = aBase + buf * ABYTES + rA * 128;
                ldm_x4(base + ((ck ^ (rA & 7)) << 4),
                       ah[mt][0], ah[mt][1], ah[mt][2], ah[mt][3]);
                ldm_x4(base + (((ck + 4) ^ (rA & 7)) << 4),
                       al[mt][0], al[mt][1], al[mt][2], al[mt][3]);
            }
#pragma unroll
            for (int np = 0; np < 2; np++) {
                int kr = ks * 16 + (lane & 15);
                int cb = wn * 4 + np * 2 + (lane >> 4);
                unsigned base = bBase + buf * BBYTES + kr * 512;
                int ph = (cb & 24) | ((cb ^ kr) & 7);
                ldm_x4t(base + (ph << 4), bh[2 * np][0], bh[2 * np][1],
                        bh[2 * np + 1][0], bh[2 * np + 1][1]);
                int cl = cb + 16;
                int pl = (cl & 24) | ((cl ^ kr) & 7);
                ldm_x4t(base + (pl << 4), bl[2 * np][0], bl[2 * np][1],
                        bl[2 * np + 1][0], bl[2 * np + 1][1]);
            }
#pragma unroll
            for (int mt = 0; mt < MT; mt++)
#pragma unroll
                for (int nt = 0; nt < 4; nt++) {
                    mma16816(acc[mt][nt], ah[mt], bh[nt]);
                    mma16816(acc[mt][nt], al[mt], bh[nt]);
                    mma16816(acc[mt][nt], ah[mt], bl[nt]);
                }
        }
    }

#pragma unroll
    for (int mt = 0; mt < MT; mt++) {
        int r1 = row0 + wm * MT * 16 + mt * 16 + (lane >> 2);
        int r2 = r1 + 8;
        float s1 = rowScale ? rowScale[rs0 + r1] : 1.f;
        float s2 = rowScale ? rowScale[rs0 + r2] : 1.f;
#pragma unroll
        for (int nt = 0; nt < 4; nt++) {
            int cidx = col0 + wn * 32 + nt * 8 + (lane & 3) * 2;
            float v0 = acc[mt][nt][0] * s1, v1 = acc[mt][nt][1] * s1;
            float v2 = acc[mt][nt][2] * s2, v3 = acc[mt][nt][3] * s2;
            if (act == 1) {
                v0 = fmaxf(v0, 0.f); v1 = fmaxf(v1, 0.f);
                v2 = fmaxf(v2, 0.f); v3 = fmaxf(v3, 0.f);
            }
            if (C) {
                *(float2*)(C + cz + (size_t)r1 * ldc + cidx) = make_float2(v0, v1);
                *(float2*)(C + cz + (size_t)r2 * ldc + cidx) = make_float2(v2, v3);
            }
            if (Chi) {
                __nv_bfloat162 h, l;
                split1(v0, h.x, l.x); split1(v1, h.y, l.y);
                *(__nv_bfloat162*)(Chi + cz + (size_t)r1 * ldc + cidx) = h;
                *(__nv_bfloat162*)(Clo + cz + (size_t)r1 * ldc + cidx) = l;
                split1(v2, h.x, l.x); split1(v3, h.y, l.y);
                *(__nv_bfloat162*)(Chi + cz + (size_t)r2 * ldc + cidx) = h;
                *(__nv_bfloat162*)(Clo + cz + (size_t)r2 * ldc + cidx) = l;
            }
        }
    }
}

// ---------------- split fp32 -> bf16 hi/lo planes ----------------
__global__ void split_k(const float* __restrict__ x, __nv_bfloat16* __restrict__ hi,
                        __nv_bfloat16* __restrict__ lo, int n) {
    int i = blockIdx.x * 256 + threadIdx.x;
    if (i < n) {
        __nv_bfloat16 h, l;
        split1(x[i], h, l);
        hi[i] = h; lo[i] = l;
    }
}

// ---------------- s,t: warp per row, 8 rows/block ----------------
__global__ void __launch_bounds__(256) st8_k(
    const float* __restrict__ h, long hStride,
    const float* __restrict__ a, long aStride, int F,
    float* __restrict__ s, float* __restrict__ t,
    unsigned* __restrict__ key) {
    int b = blockIdx.y;
    h += (long)b * hStride;
    a += (long)b * aStride;
    int w = threadIdx.x >> 5, lane = threadIdx.x & 31;
    int row = blockIdx.x * 8 + w;
    const float* hr = h + (size_t)row * F;
    float as = 0.f, at = 0.f;
    for (int k = lane * 4; k < F; k += 128) {
        float4 v = *(const float4*)(hr + k);
        float4 a0 = *(const float4*)(a + k);
        float4 a1 = *(const float4*)(a + F + k);
        as += v.x * a0.x + v.y * a0.y + v.z * a0.z + v.w * a0.w;
        at += v.x * a1.x + v.y * a1.y + v.z * a1.z + v.w * a1.w;
    }
#pragma unroll
    for (int o = 16; o > 0; o >>= 1) {
        as += __shfl_xor_sync(0xffffffffu, as, o);
        at += __shfl_xor_sync(0xffffffffu, at, o);
    }
    if (lane == 0) {
        s[b * NN + row] = as;
        t[b * NN + row] = at;
        atomicMax(&key[b], fenc(at));
    }
}

__global__ void etf_k(const float* __restrict__ t, const unsigned* __restrict__ key,
                      float* __restrict__ maxt, float* __restrict__ E,
                      float* __restrict__ Fv) {
    int b = blockIdx.y;
    float mt = fdec(key[b]);
    if (blockIdx.x == 0 && threadIdx.x == 0) maxt[b] = mt;
    int j = blockIdx.x * 512 + threadIdx.x;
    float tv = t[b * NN + j] - mt;
    E[b * NN + j] = expf(tv);
    Fv[b * NN + j] = expf(0.2f * tv);
}

// ---------------- per-row masked softmax weights, 8 rows/block ----------------
// zsel selects the parameter slot; P planes are single-slot (L2 resident).
__global__ void __launch_bounds__(256) attn8_k(
    const float* __restrict__ s, const float* __restrict__ E,
    const float* __restrict__ Fv, const float* __restrict__ maxt,
    const unsigned* __restrict__ mask,
    __nv_bfloat16* __restrict__ Phi, __nv_bfloat16* __restrict__ Plo,
    float* __restrict__ invZ) {
    __shared__ float shE[NN];
    __shared__ float shF[NN];
    int tid = threadIdx.x;
#pragma unroll
    for (int j = 0; j < 4; j++) {
        ((float4*)shE)[j * 256 + tid] = ((const float4*)E)[j * 256 + tid];
        ((float4*)shF)[j * 256 + tid] = ((const float4*)Fv)[j * 256 + tid];
    }
    __syncthreads();

    const int w = tid >> 5, lane = tid & 31;
    const int row = blockIdx.x * 8 + w;
    float q = s[row] + *maxt;
    float m = fmaxf(q, 0.2f * q);
    float c = expf(q - m);
    float d = expf(0.2f * q - m);

    const unsigned* mrow = mask + (size_t)row * 128;
    __nv_bfloat16* PhiRow = Phi + (size_t)row * NN;
    __nv_bfloat16* PloRow = Plo + (size_t)row * NN;

    float sum = 0.f;
#pragma unroll
    for (int it = 0; it < 16; it++) {
        int j0 = it * 256 + lane * 8;
        unsigned mbyte = (mrow[j0 >> 5] >> (j0 & 31)) & 0xFFu;
        float4 e0 = ((const float4*)shE)[j0 >> 2];
        float4 e1 = ((const float4*)shE)[(j0 >> 2) + 1];
        float4 f0 = ((const float4*)shF)[j0 >> 2];
        float4 f1 = ((const float4*)shF)[(j0 >> 2) + 1];
        float e[8] = {e0.x, e0.y, e0.z, e0.w, e1.x, e1.y, e1.z, e1.w};
        float f[8] = {f0.x, f0.y, f0.z, f0.w, f1.x, f1.y, f1.z, f1.w};
        __nv_bfloat16 hb[8], lb[8];
#pragma unroll
        for (int k = 0; k < 8; k++) {
            float p = ((mbyte >> k) & 1u) ? fmaxf(c * e[k], d * f[k]) : 0.f;
            sum += p;
            split1(p, hb[k], lb[k]);
        }
        *(uint4*)(PhiRow + j0) = *(const uint4*)hb;
        *(uint4*)(PloRow + j0) = *(const uint4*)lb;
    }
#pragma unroll
    for (int o = 16; o > 0; o >>= 1) sum += __shfl_xor_sync(0xffffffffu, sum, o);
    if (lane == 0) invZ[row] = 1.f / sum;
}

// ---------------- GroupNorm ----------------
__global__ void gn_reduce1_k(const float* __restrict__ h, float* __restrict__ part) {
    __shared__ float r1[256], r2[256];
    int tid = threadIdx.x;
    float s = 0.f, q = 0.f;
    for (size_t idx = (size_t)blockIdx.x * 256 + tid; idx < (size_t)NN * 1536;
         idx += (size_t)2048 * 256) {
        float v = h[idx];
        s += v;
        q += v * v;
    }
    r1[tid] = s; r2[tid] = q;
    __syncthreads();
    for (int s2 = 128; s2 > 0; s2 >>= 1) {
        if (tid < s2) { r1[tid] += r1[tid + s2]; r2[tid] += r2[tid + s2]; }
        __syncthreads();
    }
    if (tid == 0) { part[blockIdx.x] = r1[0]; part[2048 + blockIdx.x] = r2[0]; }
}

__global__ void gn_reduce2_k(const float* __restrict__ part, float* __restrict__ stats) {
    __shared__ double r1[1024], r2[1024];
    int tid = threadIdx.x;
    double s = 0.0, q = 0.0;
    for (int i = tid; i < 2048; i += 1024) { s += part[i]; q += part[2048 + i]; }
    r1[tid] = s; r2[tid] = q;
    __syncthreads();
    for (int s2 = 512; s2 > 0; s2 >>= 1) {
        if (tid < s2) { r1[tid] += r1[tid + s2]; r2[tid] += r2[tid + s2]; }
        __syncthreads();
    }
    if (tid == 0) {
        double n = (double)NN * 1536.0;
        double mu = r1[0] / n;
        double var = (r2[0] - n * mu * mu) / (n - 1.0);
        stats[0] = (float)mu;
        stats[1] = (float)(1.0 / sqrt(var + 1e-5));
    }
}

__global__ void gn_apply_k(const float* __restrict__ h, const float* __restrict__ w,
                           const float* __restrict__ b, const float* __restrict__ stats,
                           __nv_bfloat16* __restrict__ hi, __nv_bfloat16* __restrict__ lo) {
    size_t idx = (size_t)blockIdx.x * 256 + threadIdx.x;
    if (idx < (size_t)NN * 1536) {
        int c = (int)(idx % 1536);
        float v = (h[idx] - stats[0]) * stats[1] * w[c] + b[c];
        __nv_bfloat16 hh, ll;
        split1(v, hh, ll);
        hi[idx] = hh; lo[idx] = ll;
    }
}

// ---------------- host ----------------
extern "C" void kernel_launch(void* const* d_in, const int* in_sizes, int n_in,
                              void* d_out, int out_size) {
    const float* x       = (const float*)d_in[0];
    const int*   adj     = (const int*)d_in[1];
    const float* lin1_w  = (const float*)d_in[2];
    const float* lin1_b  = (const float*)d_in[3];
    const float* lin2_w  = (const float*)d_in[4];
    const float* lin2_b  = (const float*)d_in[5];
    const float* conv1_W = (const float*)d_in[6];
    const float* conv1_a = (const float*)d_in[7];
    const float* att_W   = (const float*)d_in[8];
    const float* att_a   = (const float*)d_in[9];
    const float* gn_w    = (const float*)d_in[10];
    const float* gn_b    = (const float*)d_in[11];
    const float* conv2_W = (const float*)d_in[12];
    const float* conv2_a = (const float*)d_in[13];
    float* out = (float*)d_out;

    void* p;
    cudaGetSymbolAddress(&p, g_Phi);    __nv_bfloat16* Phi = (__nv_bfloat16*)p;
    cudaGetSymbolAddress(&p, g_Plo);    __nv_bfloat16* Plo = (__nv_bfloat16*)p;
    cudaGetSymbolAddress(&p, g_hA);     float* hA = (float*)p;
    cudaGetSymbolAddress(&p, g_hAhi);   __nv_bfloat16* hAhi = (__nv_bfloat16*)p;
    cudaGetSymbolAddress(&p, g_hAlo);   __nv_bfloat16* hAlo = (__nv_bfloat16*)p;
    cudaGetSymbolAddress(&p, g_out1);   float* out1 = (float*)p;
    cudaGetSymbolAddress(&p, g_out1hi); __nv_bfloat16* out1hi = (__nv_bfloat16*)p;
    cudaGetSymbolAddress(&p, g_out1lo); __nv_bfloat16* out1lo = (__nv_bfloat16*)p;
    cudaGetSymbolAddress(&p, g_cat);    float* cat = (float*)p;
    cudaGetSymbolAddress(&p, g_cathi);  __nv_bfloat16* cathi = (__nv_bfloat16*)p;
    cudaGetSymbolAddress(&p, g_catlo);  __nv_bfloat16* catlo = (__nv_bfloat16*)p;
    cudaGetSymbolAddress(&p, g_hB6);    float* hB6 = (float*)p;
    cudaGetSymbolAddress(&p, g_hB6hi);  __nv_bfloat16* hB6hi = (__nv_bfloat16*)p;
    cudaGetSymbolAddress(&p, g_hB6lo);  __nv_bfloat16* hB6lo = (__nv_bfloat16*)p;
    cudaGetSymbolAddress(&p, g_hB);     float* hB = (float*)p;
    cudaGetSymbolAddress(&p, g_hBhi);   __nv_bfloat16* hBhi = (__nv_bfloat16*)p;
    cudaGetSymbolAddress(&p, g_hBlo);   __nv_bfloat16* hBlo = (__nv_bfloat16*)p;
    cudaGetSymbolAddress(&p, g_attWhi); __nv_bfloat16* attWhi = (__nv_bfloat16*)p;
    cudaGetSymbolAddress(&p, g_attWlo); __nv_bfloat16* attWlo = (__nv_bfloat16*)p;
    cudaGetSymbolAddress(&p, g_c2Whi);  __nv_bfloat16* c2Whi = (__nv_bfloat16*)p;
    cudaGetSymbolAddress(&p, g_c2Wlo);  __nv_bfloat16* c2Wlo = (__nv_bfloat16*)p;
    cudaGetSymbolAddress(&p, g_l1);     float* l1 = (float*)p;
    cudaGetSymbolAddress(&p, g_l2);     float* l2 = (float*)p;
    cudaGetSymbolAddress(&p, g_sv);     float* sv = (float*)p;
    cudaGetSymbolAddress(&p, g_tv);     float* tv = (float*)p;
    cudaGetSymbolAddress(&p, g_E);      float* E = (float*)p;
    cudaGetSymbolAddress(&p, g_Fv);     float* Fv = (float*)p;
    cudaGetSymbolAddress(&p, g_maxtKey);unsigned* keys = (unsigned*)p;
    cudaGetSymbolAddress(&p, g_maxt);   float* maxt = (float*)p;
    cudaGetSymbolAddress(&p, g_invZ);   float* invZ = (float*)p;
    cudaGetSymbolAddress(&p, g_mask);   unsigned* mask = (unsigned*)p;
    cudaGetSymbolAddress(&p, g_part);   float* part = (float*)p;
    cudaGetSymbolAddress(&p, g_stats);  float* stats = (float*)p;

    cudaFuncSetAttribute(mma3_k<2>, cudaFuncAttributeMaxDynamicSharedMemorySize, 98304);

    pack_mask_k<<<NN, 128>>>(adj, mask, keys);

    // lin1 + lin2 + conv1 projection (fp32)
    gemm128_k<64, 4><<<dim3(1, 32), 256>>>(x,  lin1_w, l1, 128, 128, 64, 64, lin1_b, 0);
    gemm128_k<64, 4><<<dim3(1, 32), 256>>>(l1, lin2_w, l2, 64, 64, 64, 64, lin2_b, 0);
    gemm128_k<128, 8><<<dim3(4, 32), 256>>>(l2, conv1_W, hA, 64, 64, 512, 512, nullptr, 0);
    split_k<<<(NN * 512 + 255) / 256, 256>>>(hA, hAhi, hAlo, NN * 512);

    split_k<<<(6 * 512 * 256 + 255) / 256, 256>>>(att_W, attWhi, attWlo, 6 * 512 * 256);
    split_k<<<(1536 * 256 + 255) / 256, 256>>>(conv2_W, c2Whi, c2Wlo, 1536 * 256);

    // ---- GAT conv1 (F=512): slot 0 ----
    st8_k<<<dim3(512, 1), 256>>>(hA, 0, conv1_a, 0, 512, sv, tv, keys);
    etf_k<<<dim3(8, 1), 512>>>(tv, keys, maxt, E, Fv);
    attn8_k<<<dim3(512, 1), 256>>>(sv, E, Fv, maxt, mask, Phi, Plo, invZ);
    mma3_k<2><<<dim3(4, 64, 1), 256, 98304>>>(Phi, Plo, hAhi, hAlo,
                                              out1, out1hi, out1lo,
                                              NN, NN, 512, 512, invZ, 1,
                                              0, 0, 0, 0);

    // ---- 6 head projections, batched; s/t/E/F for all heads up front ----
    mma3_k<2><<<dim3(2, 64, 6), 256, 98304>>>(out1hi, out1lo, attWhi, attWlo,
                                              hB6, hB6hi, hB6lo,
                                              512, 512, 256, 256, nullptr, 0,
                                              0, (long)512 * 256, (long)NN * 256, 0);
    st8_k<<<dim3(512, 6), 256>>>(hB6, (long)NN * 256, att_a, 512, 256,
                                 sv + NN, tv + NN, keys + 1);
    etf_k<<<dim3(8, 6), 512>>>(tv + NN, keys + 1, maxt + 1, E + NN, Fv + NN);
    // per-head: attn into the single L2-resident P slot, then GEMM
    for (int h = 0; h < 6; h++) {
        attn8_k<<<dim3(512, 1), 256>>>(sv + (1 + h) * NN, E + (1 + h) * NN,
                                       Fv + (1 + h) * NN, maxt + 1 + h, mask,
                                       Phi, Plo, invZ);
        mma3_k<2><<<dim3(2, 64, 1), 256, 98304>>>(Phi, Plo,
                                                  hB6hi + (size_t)h * NN * 256,
                                                  hB6lo + (size_t)h * NN * 256,
                                                  cat + (size_t)h * 256, nullptr, nullptr,
                                                  NN, NN, 256, 1536, invZ, 1,
                                                  0, 0, 0, 0);
    }

    // ---- GroupNorm ----
    gn_reduce1_k<<<2048, 256>>>(cat, part);
    gn_reduce2_k<<<1, 1024>>>(part, stats);
    gn_apply_k<<<(int)(((size_t)NN * 1536 + 255) / 256), 256>>>(cat, gn_w, gn_b, stats,
                                                                cathi, catlo);

    // ---- GAT conv2 (F=256): slot 7 ----
    mma3_k<2><<<dim3(2, 64, 1), 256, 98304>>>(cathi, catlo, c2Whi, c2Wlo,
                                              hB, hBhi, hBlo,
                                              1536, 1536, 256, 256, nullptr, 0,
                                              0, 0, 0, 0);
    st8_k<<<dim3(512, 1), 256>>>(hB, 0, conv2_a, 0, 256, sv + 7 * NN, tv + 7 * NN, keys + 7);
    etf_k<<<dim3(8, 1), 512>>>(tv + 7 * NN, keys + 7, maxt + 7, E + 7 * NN, Fv + 7 * NN);
    attn8_k<<<dim3(512, 1), 256>>>(sv + 7 * NN, E + 7 * NN, Fv + 7 * NN, maxt + 7, mask,
                                   Phi, Plo, invZ);
    mma3_k<2><<<dim3(2, 64, 1), 256, 98304>>>(Phi, Plo, hBhi, hBlo,
                                              out, nullptr, nullptr,
                                              NN, NN, 256, 256, invZ, 0,
                                              0, 0, 0, 0);
}

// round 14
// speedup vs baseline: 1.0868x; 1.0868x over previous
#include <cuda_runtime.h>
#include <cuda_bf16.h>
#include <cstdint>
#include <math.h>

#define NN 4096

// ---------------- scratch (device globals) ----------------
__device__ __nv_bfloat16 g_Phi[6ULL * NN * NN];
__device__ __nv_bfloat16 g_Plo[6ULL * NN * NN];
__device__ float g_hA[NN * 512];
__device__ __nv_bfloat16 g_hAhi[NN * 512];
__device__ __nv_bfloat16 g_hAlo[NN * 512];
__device__ __nv_bfloat16 g_out1hi[NN * 512];
__device__ __nv_bfloat16 g_out1lo[NN * 512];
__device__ float g_cat[NN * 1536];
__device__ __nv_bfloat16 g_cathi[NN * 1536];
__device__ __nv_bfloat16 g_catlo[NN * 1536];
__device__ __nv_bfloat16 g_hB6hi[6 * NN * 256];
__device__ __nv_bfloat16 g_hB6lo[6 * NN * 256];
__device__ __nv_bfloat16 g_hBhi[NN * 256];
__device__ __nv_bfloat16 g_hBlo[NN * 256];
__device__ __nv_bfloat16 g_attWhi[6 * 512 * 256];
__device__ __nv_bfloat16 g_attWlo[6 * 512 * 256];
__device__ __nv_bfloat16 g_c2Whi[1536 * 256];
__device__ __nv_bfloat16 g_c2Wlo[1536 * 256];
__device__ float g_l1[NN * 64];
__device__ float g_l2[NN * 64];
__device__ float g_sv[8 * NN];
__device__ float g_tv[8 * NN];
__device__ float g_E[8 * NN];
__device__ float g_Fv[8 * NN];
__device__ unsigned g_maxtKey[8];
__device__ float g_maxt[8];
__device__ float g_invZ[8 * NN];
__device__ unsigned g_mask[NN * 128];
__device__ float g_part[2 * 2048];
__device__ float g_stats[2];

__device__ __forceinline__ unsigned fenc(float f) {
    unsigned u = __float_as_uint(f);
    return (u & 0x80000000u) ? ~u : (u | 0x80000000u);
}
__device__ __forceinline__ float fdec(unsigned k) {
    unsigned u = (k & 0x80000000u) ? (k & 0x7fffffffu) : ~k;
    return __uint_as_float(u);
}
__device__ __forceinline__ unsigned sptr(const void* p) {
    return (unsigned)__cvta_generic_to_shared(p);
}
__device__ __forceinline__ void cpasync16(unsigned s, const void* g) {
    asm volatile("cp.async.cg.shared.global [%0], [%1], 16;\n" :: "r"(s), "l"(g));
}
__device__ __forceinline__ void ldm_x4(unsigned a, unsigned& r0, unsigned& r1,
                                       unsigned& r2, unsigned& r3) {
    asm volatile("ldmatrix.sync.aligned.m8n8.x4.shared.b16 {%0,%1,%2,%3}, [%4];"
                 : "=r"(r0), "=r"(r1), "=r"(r2), "=r"(r3) : "r"(a));
}
__device__ __forceinline__ void ldm_x4t(unsigned a, unsigned& r0, unsigned& r1,
                                        unsigned& r2, unsigned& r3) {
    asm volatile("ldmatrix.sync.aligned.m8n8.x4.trans.shared.b16 {%0,%1,%2,%3}, [%4];"
                 : "=r"(r0), "=r"(r1), "=r"(r2), "=r"(r3) : "r"(a));
}
__device__ __forceinline__ void mma16816(float* c, const unsigned* a, const unsigned* b) {
    asm volatile(
        "mma.sync.aligned.m16n8k16.row.col.f32.bf16.bf16.f32 "
        "{%0,%1,%2,%3},{%4,%5,%6,%7},{%8,%9},{%0,%1,%2,%3};"
        : "+f"(c[0]), "+f"(c[1]), "+f"(c[2]), "+f"(c[3])
        : "r"(a[0]), "r"(a[1]), "r"(a[2]), "r"(a[3]), "r"(b[0]), "r"(b[1]));
}
__device__ __forceinline__ void split1(float v, __nv_bfloat16& hi, __nv_bfloat16& lo) {
    hi = __float2bfloat16(v);
    lo = __float2bfloat16(v - __bfloat162float(hi));
}

// ---------------- bitmask pack + maxt reset ----------------
__global__ void pack_mask_k(const int* __restrict__ adj, unsigned* __restrict__ mask,
                            unsigned* __restrict__ keys) {
    int i = blockIdx.x;
    int w = threadIdx.x;
    if (i == 0 && w < 8) keys[w] = 0u;
    const int* row = adj + (size_t)i * NN + w * 32;
    unsigned bits = 0;
#pragma unroll
    for (int b = 0; b < 32; b++) bits |= (row[b] > 0 ? 1u : 0u) << b;
    mask[i * 128 + w] = bits;
}

// ---------------- fp32 GEMM for the small projections ----------------
template <int BN, int TN>
__global__ void __launch_bounds__(256) gemm128_k(
    const float* __restrict__ A, const float* __restrict__ B, float* __restrict__ C,
    int K, int lda, int ldb, int ldc,
    const float* __restrict__ bias, int act) {
    __shared__ float As[2][16][128];
    __shared__ float Bs[2][16][BN];
    const int tid = threadIdx.x;
    const int tx = tid & 15, ty = tid >> 4;
    const int row0 = blockIdx.y * 128, col0 = blockIdx.x * BN;
    int am[2], akq[2];
#pragma unroll
    for (int i = 0; i < 2; i++) {
        int idx = tid + i * 256;
        am[i] = idx >> 2;
        akq[i] = (idx & 3) << 2;
    }
    constexpr int BCNT = (16 * BN / 4) / 256;
    int bk[BCNT], bn[BCNT];
#pragma unroll
    for (int i = 0; i < BCNT; i++) {
        int idx = tid + i * 256;
        bk[i] = idx / (BN / 4);
        bn[i] = (idx % (BN / 4)) << 2;
    }
    float acc[8][TN];
#pragma unroll
    for (int i = 0; i < 8; i++)
#pragma unroll
        for (int j = 0; j < TN; j++) acc[i][j] = 0.f;
    float4 aR[2];
    float4 bR[BCNT];
#pragma unroll
    for (int i = 0; i < 2; i++)
        aR[i] = *(const float4*)(A + (size_t)(row0 + am[i]) * lda + akq[i]);
#pragma unroll
    for (int i = 0; i < BCNT; i++)
        bR[i] = *(const float4*)(B + (size_t)bk[i] * ldb + col0 + bn[i]);
#pragma unroll
    for (int i = 0; i < 2; i++) {
        As[0][akq[i] + 0][am[i]] = aR[i].x;
        As[0][akq[i] + 1][am[i]] = aR[i].y;
        As[0][akq[i] + 2][am[i]] = aR[i].z;
        As[0][akq[i] + 3][am[i]] = aR[i].w;
    }
#pragma unroll
    for (int i = 0; i < BCNT; i++) *(float4*)&Bs[0][bk[i]][bn[i]] = bR[i];
    __syncthreads();
    const int nT = K >> 4;
    for (int t = 0; t < nT; t++) {
        const int buf = t & 1;
        if (t + 1 < nT) {
            const int k0 = (t + 1) << 4;
#pragma unroll
            for (int i = 0; i < 2; i++)
                aR[i] = *(const float4*)(A + (size_t)(row0 + am[i]) * lda + k0 + akq[i]);
#pragma unroll
            for (int i = 0; i < BCNT; i++)
                bR[i] = *(const float4*)(B + (size_t)(k0 + bk[i]) * ldb + col0 + bn[i]);
        }
#pragma unroll
        for (int kk = 0; kk < 16; kk++) {
            float4 a0 = *(const float4*)&As[buf][kk][ty * 8];
            float4 a1 = *(const float4*)&As[buf][kk][ty * 8 + 4];
            float av[8] = {a0.x, a0.y, a0.z, a0.w, a1.x, a1.y, a1.z, a1.w};
            float bv[TN];
            float4 b0 = *(const float4*)&Bs[buf][kk][tx * TN];
            bv[0] = b0.x; bv[1] = b0.y; bv[2] = b0.z; bv[3] = b0.w;
            if (TN == 8) {
                float4 b1 = *(const float4*)&Bs[buf][kk][tx * TN + 4];
                bv[4] = b1.x; bv[5] = b1.y; bv[6] = b1.z; bv[7] = b1.w;
            }
#pragma unroll
            for (int i = 0; i < 8; i++)
#pragma unroll
                for (int j = 0; j < TN; j++) acc[i][j] += av[i] * bv[j];
        }
        if (t + 1 < nT) {
            const int nb = buf ^ 1;
#pragma unroll
            for (int i = 0; i < 2; i++) {
                As[nb][akq[i] + 0][am[i]] = aR[i].x;
                As[nb][akq[i] + 1][am[i]] = aR[i].y;
                As[nb][akq[i] + 2][am[i]] = aR[i].z;
                As[nb][akq[i] + 3][am[i]] = aR[i].w;
            }
#pragma unroll
            for (int i = 0; i < BCNT; i++) *(float4*)&Bs[nb][bk[i]][bn[i]] = bR[i];
            __syncthreads();
        }
    }
#pragma unroll
    for (int i = 0; i < 8; i++) {
        int row = row0 + ty * 8 + i;
#pragma unroll
        for (int j4 = 0; j4 < TN; j4 += 4) {
            float r[4];
#pragma unroll
            for (int j = 0; j < 4; j++) {
                float x = acc[i][j4 + j];
                if (bias) x += bias[col0 + tx * TN + j4 + j];
                if (act == 1) x = fmaxf(x, 0.f);
                r[j] = x;
            }
            *(float4*)(C + (size_t)row * ldc + col0 + tx * TN + j4) =
                make_float4(r[0], r[1], r[2], r[3]);
        }
    }
}

// ---------------- 3xBF16 tensor-core GEMM, 4-stage pipeline, 2 CTAs/SM ----------------
template <int MT>
__global__ void __launch_bounds__(256, 2) mma3_k(
    const __nv_bfloat16* __restrict__ Ahi, const __nv_bfloat16* __restrict__ Alo,
    const __nv_bfloat16* __restrict__ Bhi, const __nv_bfloat16* __restrict__ Blo,
    float* __restrict__ C, __nv_bfloat16* __restrict__ Chi, __nv_bfloat16* __restrict__ Clo,
    int K, int lda, int ldb, int ldc,
    const float* __restrict__ rowScale, int act,
    long strideAz, long strideBz, long strideCz, int rsStride) {
    constexpr int BM = MT * 32;
    constexpr int ABYTES = BM * 128;
    constexpr int BBYTES = 32 * 512;
    constexpr int LA = BM / 32;

    extern __shared__ __align__(16) char smraw[];
    unsigned aBase = sptr(smraw);
    unsigned bBase = aBase + 4 * ABYTES;

    const int z = blockIdx.z;
    Ahi += (long)z * strideAz;
    Alo += (long)z * strideAz;
    Bhi += (long)z * strideBz;
    Blo += (long)z * strideBz;
    long cz = (long)z * strideCz;
    const int rs0 = z * rsStride;

    const int tid = threadIdx.x;
    const int w = tid >> 5, lane = tid & 31;
    const int wm = w >> 2, wn = w & 3;
    const int row0 = blockIdx.y * BM, col0 = blockIdx.x * 128;
    const int nT = K >> 5;

    auto loadTile = [&](int buf, int k0) {
#pragma unroll
        for (int i = 0; i < LA; i++) {
            int idx = i * 256 + tid;
            int plane = idx >= BM * 4 ? 1 : 0;
            int ii = idx - plane * BM * 4;
            int r = ii >> 2, c4 = ii & 3;
            const __nv_bfloat16* g =
                (plane ? Alo : Ahi) + (size_t)(row0 + r) * lda + k0 + c4 * 8;
            int c = c4 + plane * 4;
            cpasync16(aBase + buf * ABYTES + r * 128 + ((c ^ (r & 7)) << 4), g);
        }
#pragma unroll
        for (int i = 0; i < 4; i++) {
            int idx = i * 256 + tid;
            int plane = idx >> 9;
            int ii = idx & 511;
            int k = ii >> 4, c16 = ii & 15;
            const __nv_bfloat16* g =
                (plane ? Blo : Bhi) + (size_t)(k0 + k) * ldb + col0 + c16 * 8;
            int c = c16 + plane * 16;
            int p = (c & 24) | ((c ^ k) & 7);
            cpasync16(bBase + buf * BBYTES + k * 512 + (p << 4), g);
        }
    };

    float acc[MT][4][4];
#pragma unroll
    for (int m = 0; m < MT; m++)
#pragma unroll
        for (int n = 0; n < 4; n++)
#pragma unroll
            for (int q = 0; q < 4; q++) acc[m][n][q] = 0.f;

    loadTile(0, 0);
    asm volatile("cp.async.commit_group;\n" ::);
    loadTile(1, 32);
    asm volatile("cp.async.commit_group;\n" ::);
    loadTile(2, 64);
    asm volatile("cp.async.commit_group;\n" ::);

    for (int t = 0; t < nT; t++) {
        asm volatile("cp.async.wait_group 2;\n" ::);
        __syncthreads();
        if (t + 3 < nT) {
            loadTile((t + 3) & 3, (t + 3) * 32);
        }
        asm volatile("cp.async.commit_group;\n" ::);

        const int buf = t & 3;
#pragma unroll
        for (int ks = 0; ks < 2; ks++) {
            unsigned ah[MT][4], al[MT][4], bh[4][2], bl[4][2];
#pragma unroll
            for (int mt = 0; mt < MT; mt++) {
                int rA = wm * MT * 16 + mt * 16 + (lane & 15);
                int ck = ks * 2 + (lane >> 4);
                unsigned base = aBase + buf * ABYTES + rA * 128;
                ldm_x4(base + ((ck ^ (rA & 7)) << 4),
                       ah[mt][0], ah[mt][1], ah[mt][2], ah[mt][3]);
                ldm_x4(base + (((ck + 4) ^ (rA & 7)) << 4),
                       al[mt][0], al[mt][1], al[mt][2], al[mt][3]);
            }
#pragma unroll
            for (int np = 0; np < 2; np++) {
                int kr = ks * 16 + (lane & 15);
                int cb = wn * 4 + np * 2 + (lane >> 4);
                unsigned base = bBase + buf * BBYTES + kr * 512;
                int ph = (cb & 24) | ((cb ^ kr) & 7);
                ldm_x4t(base + (ph << 4), bh[2 * np][0], bh[2 * np][1],
                        bh[2 * np + 1][0], bh[2 * np + 1][1]);
                int cl = cb + 16;
                int pl = (cl & 24) | ((cl ^ kr) & 7);
                ldm_x4t(base + (pl << 4), bl[2 * np][0], bl[2 * np][1],
                        bl[2 * np + 1][0], bl[2 * np + 1][1]);
            }
#pragma unroll
            for (int mt = 0; mt < MT; mt++)
#pragma unroll
                for (int nt = 0; nt < 4; nt++) {
                    mma16816(acc[mt][nt], ah[mt], bh[nt]);
                    mma16816(acc[mt][nt], al[mt], bh[nt]);
                    mma16816(acc[mt][nt], ah[mt], bl[nt]);
                }
        }
    }

#pragma unroll
    for (int mt = 0; mt < MT; mt++) {
        int r1 = row0 + wm * MT * 16 + mt * 16 + (lane >> 2);
        int r2 = r1 + 8;
        float s1 = rowScale ? rowScale[rs0 + r1] : 1.f;
        float s2 = rowScale ? rowScale[rs0 + r2] : 1.f;
#pragma unroll
        for (int nt = 0; nt < 4; nt++) {
            int cidx = col0 + wn * 32 + nt * 8 + (lane & 3) * 2;
            float v0 = acc[mt][nt][0] * s1, v1 = acc[mt][nt][1] * s1;
            float v2 = acc[mt][nt][2] * s2, v3 = acc[mt][nt][3] * s2;
            if (act == 1) {
                v0 = fmaxf(v0, 0.f); v1 = fmaxf(v1, 0.f);
                v2 = fmaxf(v2, 0.f); v3 = fmaxf(v3, 0.f);
            }
            if (C) {
                *(float2*)(C + cz + (size_t)r1 * ldc + cidx) = make_float2(v0, v1);
                *(float2*)(C + cz + (size_t)r2 * ldc + cidx) = make_float2(v2, v3);
            }
            if (Chi) {
                __nv_bfloat162 h, l;
                split1(v0, h.x, l.x); split1(v1, h.y, l.y);
                *(__nv_bfloat162*)(Chi + cz + (size_t)r1 * ldc + cidx) = h;
                *(__nv_bfloat162*)(Clo + cz + (size_t)r1 * ldc + cidx) = l;
                split1(v2, h.x, l.x); split1(v3, h.y, l.y);
                *(__nv_bfloat162*)(Chi + cz + (size_t)r2 * ldc + cidx) = h;
                *(__nv_bfloat162*)(Clo + cz + (size_t)r2 * ldc + cidx) = l;
            }
        }
    }
}

// ---------------- split fp32 -> bf16 hi/lo planes ----------------
__global__ void split_k(const float* __restrict__ x, __nv_bfloat16* __restrict__ hi,
                        __nv_bfloat16* __restrict__ lo, int n) {
    int i = blockIdx.x * 256 + threadIdx.x;
    if (i < n) {
        __nv_bfloat16 h, l;
        split1(x[i], h, l);
        hi[i] = h; lo[i] = l;
    }
}

// ---------------- s,t from fp32 h: warp per row, 8 rows/block ----------------
__global__ void __launch_bounds__(256) st8_k(
    const float* __restrict__ h, long hStride,
    const float* __restrict__ a, long aStride, int F,
    float* __restrict__ s, float* __restrict__ t,
    unsigned* __restrict__ key) {
    int b = blockIdx.y;
    h += (long)b * hStride;
    a += (long)b * aStride;
    int w = threadIdx.x >> 5, lane = threadIdx.x & 31;
    int row = blockIdx.x * 8 + w;
    const float* hr = h + (size_t)row * F;
    float as = 0.f, at = 0.f;
    for (int k = lane * 4; k < F; k += 128) {
        float4 v = *(const float4*)(hr + k);
        float4 a0 = *(const float4*)(a + k);
        float4 a1 = *(const float4*)(a + F + k);
        as += v.x * a0.x + v.y * a0.y + v.z * a0.z + v.w * a0.w;
        at += v.x * a1.x + v.y * a1.y + v.z * a1.z + v.w * a1.w;
    }
#pragma unroll
    for (int o = 16; o > 0; o >>= 1) {
        as += __shfl_xor_sync(0xffffffffu, as, o);
        at += __shfl_xor_sync(0xffffffffu, at, o);
    }
    if (lane == 0) {
        s[b * NN + row] = as;
        t[b * NN + row] = at;
        atomicMax(&key[b], fenc(at));
    }
}

// ---------------- s,t from bf16 hi/lo planes: warp per row, 8 rows/block ----------------
__global__ void __launch_bounds__(256) st8hl_k(
    const __nv_bfloat16* __restrict__ hhi, const __nv_bfloat16* __restrict__ hlo,
    long hStride, const float* __restrict__ a, long aStride, int F,
    float* __restrict__ s, float* __restrict__ t,
    unsigned* __restrict__ key) {
    int b = blockIdx.y;
    hhi += (long)b * hStride;
    hlo += (long)b * hStride;
    a += (long)b * aStride;
    int w = threadIdx.x >> 5, lane = threadIdx.x & 31;
    int row = blockIdx.x * 8 + w;
    const __nv_bfloat16* hr = hhi + (size_t)row * F;
    const __nv_bfloat16* lr = hlo + (size_t)row * F;
    float as = 0.f, at = 0.f;
    for (int k = lane * 8; k < F; k += 256) {
        uint4 hv = *(const uint4*)(hr + k);
        uint4 lv = *(const uint4*)(lr + k);
        const __nv_bfloat16* hb = (const __nv_bfloat16*)&hv;
        const __nv_bfloat16* lb = (const __nv_bfloat16*)&lv;
#pragma unroll
        for (int q = 0; q < 8; q++) {
            float v = __bfloat162float(hb[q]) + __bfloat162float(lb[q]);
            as += v * a[k + q];
            at += v * a[F + k + q];
        }
    }
#pragma unroll
    for (int o = 16; o > 0; o >>= 1) {
        as += __shfl_xor_sync(0xffffffffu, as, o);
        at += __shfl_xor_sync(0xffffffffu, at, o);
    }
    if (lane == 0) {
        s[b * NN + row] = as;
        t[b * NN + row] = at;
        atomicMax(&key[b], fenc(at));
    }
}

__global__ void etf_k(const float* __restrict__ t, const unsigned* __restrict__ key,
                      float* __restrict__ maxt, float* __restrict__ E,
                      float* __restrict__ Fv) {
    int b = blockIdx.y;
    float mt = fdec(key[b]);
    if (blockIdx.x == 0 && threadIdx.x == 0) maxt[b] = mt;
    int j = blockIdx.x * 512 + threadIdx.x;
    float tv = t[b * NN + j] - mt;
    E[b * NN + j] = expf(tv);
    Fv[b * NN + j] = expf(0.2f * tv);
}

// ---------------- per-row masked softmax weights, 8 rows/block, z-batched ----------------
__global__ void __launch_bounds__(256) attn8_k(
    const float* __restrict__ s, const float* __restrict__ E,
    const float* __restrict__ Fv, const float* __restrict__ maxt,
    const unsigned* __restrict__ mask,
    __nv_bfloat16* __restrict__ Phi, __nv_bfloat16* __restrict__ Plo,
    float* __restrict__ invZ) {
    __shared__ float shE[NN];
    __shared__ float shF[NN];
    const int z = blockIdx.y;
    s += (size_t)z * NN;
    E += (size_t)z * NN;
    Fv += (size_t)z * NN;
    Phi += (size_t)z * NN * NN;
    Plo += (size_t)z * NN * NN;
    invZ += (size_t)z * NN;

    int tid = threadIdx.x;
#pragma unroll
    for (int j = 0; j < 4; j++) {
        ((float4*)shE)[j * 256 + tid] = ((const float4*)E)[j * 256 + tid];
        ((float4*)shF)[j * 256 + tid] = ((const float4*)Fv)[j * 256 + tid];
    }
    __syncthreads();

    const int w = tid >> 5, lane = tid & 31;
    const int row = blockIdx.x * 8 + w;
    float q = s[row] + maxt[z];
    float m = fmaxf(q, 0.2f * q);
    float c = expf(q - m);
    float d = expf(0.2f * q - m);

    const unsigned* mrow = mask + (size_t)row * 128;
    __nv_bfloat16* PhiRow = Phi + (size_t)row * NN;
    __nv_bfloat16* PloRow = Plo + (size_t)row * NN;

    float sum = 0.f;
#pragma unroll
    for (int it = 0; it < 16; it++) {
        int j0 = it * 256 + lane * 8;
        unsigned mbyte = (mrow[j0 >> 5] >> (j0 & 31)) & 0xFFu;
        float4 e0 = ((const float4*)shE)[j0 >> 2];
        float4 e1 = ((const float4*)shE)[(j0 >> 2) + 1];
        float4 f0 = ((const float4*)shF)[j0 >> 2];
        float4 f1 = ((const float4*)shF)[(j0 >> 2) + 1];
        float e[8] = {e0.x, e0.y, e0.z, e0.w, e1.x, e1.y, e1.z, e1.w};
        float f[8] = {f0.x, f0.y, f0.z, f0.w, f1.x, f1.y, f1.z, f1.w};
        __nv_bfloat16 hb[8], lb[8];
#pragma unroll
        for (int k = 0; k < 8; k++) {
            float p = ((mbyte >> k) & 1u) ? fmaxf(c * e[k], d * f[k]) : 0.f;
            sum += p;
            split1(p, hb[k], lb[k]);
        }
        *(uint4*)(PhiRow + j0) = *(const uint4*)hb;
        *(uint4*)(PloRow + j0) = *(const uint4*)lb;
    }
#pragma unroll
    for (int o = 16; o > 0; o >>= 1) sum += __shfl_xor_sync(0xffffffffu, sum, o);
    if (lane == 0) invZ[row] = 1.f / sum;
}

// ---------------- GroupNorm ----------------
__global__ void gn_reduce1_k(const float* __restrict__ h, float* __restrict__ part) {
    __shared__ float r1[256], r2[256];
    int tid = threadIdx.x;
    float s = 0.f, q = 0.f;
    for (size_t idx = (size_t)blockIdx.x * 256 + tid; idx < (size_t)NN * 1536;
         idx += (size_t)2048 * 256) {
        float v = h[idx];
        s += v;
        q += v * v;
    }
    r1[tid] = s; r2[tid] = q;
    __syncthreads();
    for (int s2 = 128; s2 > 0; s2 >>= 1) {
        if (tid < s2) { r1[tid] += r1[tid + s2]; r2[tid] += r2[tid + s2]; }
        __syncthreads();
    }
    if (tid == 0) { part[blockIdx.x] = r1[0]; part[2048 + blockIdx.x] = r2[0]; }
}

__global__ void gn_reduce2_k(const float* __restrict__ part, float* __restrict__ stats) {
    __shared__ double r1[1024], r2[1024];
    int tid = threadIdx.x;
    double s = 0.0, q = 0.0;
    for (int i = tid; i < 2048; i += 1024) { s += part[i]; q += part[2048 + i]; }
    r1[tid] = s; r2[tid] = q;
    __syncthreads();
    for (int s2 = 512; s2 > 0; s2 >>= 1) {
        if (tid < s2) { r1[tid] += r1[tid + s2]; r2[tid] += r2[tid + s2]; }
        __syncthreads();
    }
    if (tid == 0) {
        double n = (double)NN * 1536.0;
        double mu = r1[0] / n;
        double var = (r2[0] - n * mu * mu) / (n - 1.0);
        stats[0] = (float)mu;
        stats[1] = (float)(1.0 / sqrt(var + 1e-5));
    }
}

__global__ void gn_apply_k(const float* __restrict__ h, const float* __restrict__ w,
                           const float* __restrict__ b, const float* __restrict__ stats,
                           __nv_bfloat16* __restrict__ hi, __nv_bfloat16* __restrict__ lo) {
    size_t idx = (size_t)blockIdx.x * 256 + threadIdx.x;
    if (idx < (size_t)NN * 1536) {
        int c = (int)(idx % 1536);
        float v = (h[idx] - stats[0]) * stats[1] * w[c] + b[c];
        __nv_bfloat16 hh, ll;
        split1(v, hh, ll);
        hi[idx] = hh; lo[idx] = ll;
    }
}

// ---------------- host ----------------
extern "C" void kernel_launch(void* const* d_in, const int* in_sizes, int n_in,
                              void* d_out, int out_size) {
    const float* x       = (const float*)d_in[0];
    const int*   adj     = (const int*)d_in[1];
    const float* lin1_w  = (const float*)d_in[2];
    const float* lin1_b  = (const float*)d_in[3];
    const float* lin2_w  = (const float*)d_in[4];
    const float* lin2_b  = (const float*)d_in[5];
    const float* conv1_W = (const float*)d_in[6];
    const float* conv1_a = (const float*)d_in[7];
    const float* att_W   = (const float*)d_in[8];
    const float* att_a   = (const float*)d_in[9];
    const float* gn_w    = (const float*)d_in[10];
    const float* gn_b    = (const float*)d_in[11];
    const float* conv2_W = (const float*)d_in[12];
    const float* conv2_a = (const float*)d_in[13];
    float* out = (float*)d_out;

    void* p;
    cudaGetSymbolAddress(&p, g_Phi);    __nv_bfloat16* Phi = (__nv_bfloat16*)p;
    cudaGetSymbolAddress(&p, g_Plo);    __nv_bfloat16* Plo = (__nv_bfloat16*)p;
    cudaGetSymbolAddress(&p, g_hA);     float* hA = (float*)p;
    cudaGetSymbolAddress(&p, g_hAhi);   __nv_bfloat16* hAhi = (__nv_bfloat16*)p;
    cudaGetSymbolAddress(&p, g_hAlo);   __nv_bfloat16* hAlo = (__nv_bfloat16*)p;
    cudaGetSymbolAddress(&p, g_out1hi); __nv_bfloat16* out1hi = (__nv_bfloat16*)p;
    cudaGetSymbolAddress(&p, g_out1lo); __nv_bfloat16* out1lo = (__nv_bfloat16*)p;
    cudaGetSymbolAddress(&p, g_cat);    float* cat = (float*)p;
    cudaGetSymbolAddress(&p, g_cathi);  __nv_bfloat16* cathi = (__nv_bfloat16*)p;
    cudaGetSymbolAddress(&p, g_catlo);  __nv_bfloat16* catlo = (__nv_bfloat16*)p;
    cudaGetSymbolAddress(&p, g_hB6hi);  __nv_bfloat16* hB6hi = (__nv_bfloat16*)p;
    cudaGetSymbolAddress(&p, g_hB6lo);  __nv_bfloat16* hB6lo = (__nv_bfloat16*)p;
    cudaGetSymbolAddress(&p, g_hBhi);   __nv_bfloat16* hBhi = (__nv_bfloat16*)p;
    cudaGetSymbolAddress(&p, g_hBlo);   __nv_bfloat16* hBlo = (__nv_bfloat16*)p;
    cudaGetSymbolAddress(&p, g_attWhi); __nv_bfloat16* attWhi = (__nv_bfloat16*)p;
    cudaGetSymbolAddress(&p, g_attWlo); __nv_bfloat16* attWlo = (__nv_bfloat16*)p;
    cudaGetSymbolAddress(&p, g_c2Whi);  __nv_bfloat16* c2Whi = (__nv_bfloat16*)p;
    cudaGetSymbolAddress(&p, g_c2Wlo);  __nv_bfloat16* c2Wlo = (__nv_bfloat16*)p;
    cudaGetSymbolAddress(&p, g_l1);     float* l1 = (float*)p;
    cudaGetSymbolAddress(&p, g_l2);     float* l2 = (float*)p;
    cudaGetSymbolAddress(&p, g_sv);     float* sv = (float*)p;
    cudaGetSymbolAddress(&p, g_tv);     float* tv = (float*)p;
    cudaGetSymbolAddress(&p, g_E);      float* E = (float*)p;
    cudaGetSymbolAddress(&p, g_Fv);     float* Fv = (float*)p;
    cudaGetSymbolAddress(&p, g_maxtKey);unsigned* keys = (unsigned*)p;
    cudaGetSymbolAddress(&p, g_maxt);   float* maxt = (float*)p;
    cudaGetSymbolAddress(&p, g_invZ);   float* invZ = (float*)p;
    cudaGetSymbolAddress(&p, g_mask);   unsigned* mask = (unsigned*)p;
    cudaGetSymbolAddress(&p, g_part);   float* part = (float*)p;
    cudaGetSymbolAddress(&p, g_stats);  float* stats = (float*)p;

    cudaFuncSetAttribute(mma3_k<2>, cudaFuncAttributeMaxDynamicSharedMemorySize, 98304);

    pack_mask_k<<<NN, 128>>>(adj, mask, keys);

    // lin1 + lin2 + conv1 projection (fp32)
    gemm128_k<64, 4><<<dim3(1, 32), 256>>>(x,  lin1_w, l1, 128, 128, 64, 64, lin1_b, 0);
    gemm128_k<64, 4><<<dim3(1, 32), 256>>>(l1, lin2_w, l2, 64, 64, 64, 64, lin2_b, 0);
    gemm128_k<128, 8><<<dim3(4, 32), 256>>>(l2, conv1_W, hA, 64, 64, 512, 512, nullptr, 0);
    split_k<<<(NN * 512 + 255) / 256, 256>>>(hA, hAhi, hAlo, NN * 512);

    split_k<<<(6 * 512 * 256 + 255) / 256, 256>>>(att_W, attWhi, attWlo, 6 * 512 * 256);
    split_k<<<(1536 * 256 + 255) / 256, 256>>>(conv2_W, c2Whi, c2Wlo, 1536 * 256);

    // ---- GAT conv1 (F=512): P slot 0, invZ slot 0 ----
    st8_k<<<dim3(512, 1), 256>>>(hA, 0, conv1_a, 0, 512, sv, tv, keys);
    etf_k<<<dim3(8, 1), 512>>>(tv, keys, maxt, E, Fv);
    attn8_k<<<dim3(512, 1), 256>>>(sv, E, Fv, maxt, mask, Phi, Plo, invZ);
    mma3_k<2><<<dim3(4, 64, 1), 256, 98304>>>(Phi, Plo, hAhi, hAlo,
                                              nullptr, out1hi, out1lo,
                                              NN, NN, 512, 512, invZ, 1,
                                              0, 0, 0, 0);

    // ---- 6 head projections, batched (bf16 planes only) ----
    mma3_k<2><<<dim3(2, 64, 6), 256, 98304>>>(out1hi, out1lo, attWhi, attWlo,
                                              nullptr, hB6hi, hB6lo,
                                              512, 512, 256, 256, nullptr, 0,
                                              0, (long)512 * 256, (long)NN * 256, 0);
    st8hl_k<<<dim3(512, 6), 256>>>(hB6hi, hB6lo, (long)NN * 256, att_a, 512, 256,
                                   sv + NN, tv + NN, keys + 1);
    etf_k<<<dim3(8, 6), 512>>>(tv + NN, keys + 1, maxt + 1, E + NN, Fv + NN);
    attn8_k<<<dim3(512, 6), 256>>>(sv + NN, E + NN, Fv + NN, maxt + 1, mask,
                                   Phi, Plo, invZ);
    mma3_k<2><<<dim3(2, 64, 6), 256, 98304>>>(Phi, Plo, hB6hi, hB6lo,
                                              cat, nullptr, nullptr,
                                              NN, NN, 256, 1536, invZ, 1,
                                              (long)NN * NN, (long)NN * 256, 256, NN);

    // ---- GroupNorm ----
    gn_reduce1_k<<<2048, 256>>>(cat, part);
    gn_reduce2_k<<<1, 1024>>>(part, stats);
    gn_apply_k<<<(int)(((size_t)NN * 1536 + 255) / 256), 256>>>(cat, gn_w, gn_b, stats,
                                                                cathi, catlo);

    // ---- GAT conv2 (F=256): P slot 0, invZ slot 0, data slot 7 ----
    mma3_k<2><<<dim3(2, 64, 1), 256, 98304>>>(cathi, catlo, c2Whi, c2Wlo,
                                              nullptr, hBhi, hBlo,
                                              1536, 1536, 256, 256, nullptr, 0,
                                              0, 0, 0, 0);
    st8hl_k<<<dim3(512, 1), 256>>>(hBhi, hBlo, 0, conv2_a, 0, 256,
                                   sv + 7 * NN, tv + 7 * NN, keys + 7);
    etf_k<<<dim3(8, 1), 512>>>(tv + 7 * NN, keys + 7, maxt + 7, E + 7 * NN, Fv + 7 * NN);
    attn8_k<<<dim3(512, 1), 256>>>(sv + 7 * NN, E + 7 * NN, Fv + 7 * NN, maxt + 7, mask,
                                   Phi, Plo, invZ);
    mma3_k<2><<<dim3(2, 64, 1), 256, 98304>>>(Phi, Plo, hBhi, hBlo,
                                              out, nullptr, nullptr,
                                              NN, NN, 256, 256, invZ, 0,
                                              0, 0, 0, 0);
}

// round 15
// speedup vs baseline: 1.3564x; 1.2481x over previous
#include <cuda_runtime.h>
#include <cuda_fp16.h>
#include <cstdint>
#include <math.h>

#define NN 4096

// ---------------- scratch (device globals) ----------------
__device__ __half g_Pf[6ULL * NN * NN];          // 6 P slots, single fp16 plane
__device__ float g_hA[NN * 512];
__device__ __half g_hAhi[NN * 512];
__device__ __half g_hAlo[NN * 512];
__device__ __half g_out1hi[NN * 512];
__device__ __half g_out1lo[NN * 512];
__device__ float g_cat[NN * 1536];
__device__ __half g_cathi[NN * 1536];
__device__ __half g_catlo[NN * 1536];
__device__ __half g_hB6hi[6 * NN * 256];
__device__ __half g_hB6lo[6 * NN * 256];
__device__ __half g_hBhi[NN * 256];
__device__ __half g_hBlo[NN * 256];
__device__ __half g_attWhi[6 * 512 * 256];
__device__ __half g_attWlo[6 * 512 * 256];
__device__ __half g_c2Whi[1536 * 256];
__device__ __half g_c2Wlo[1536 * 256];
__device__ float g_l1[NN * 64];
__device__ float g_l2[NN * 64];
__device__ float g_sv[8 * NN];
__device__ float g_tv[8 * NN];
__device__ float g_E[8 * NN];
__device__ float g_Fv[8 * NN];
__device__ unsigned g_maxtKey[8];
__device__ float g_maxt[8];
__device__ float g_invZ[8 * NN];
__device__ unsigned g_mask[NN * 128];
__device__ float g_part[2 * 2048];
__device__ float g_stats[2];

__device__ __forceinline__ unsigned fenc(float f) {
    unsigned u = __float_as_uint(f);
    return (u & 0x80000000u) ? ~u : (u | 0x80000000u);
}
__device__ __forceinline__ float fdec(unsigned k) {
    unsigned u = (k & 0x80000000u) ? (k & 0x7fffffffu) : ~k;
    return __uint_as_float(u);
}
__device__ __forceinline__ unsigned sptr(const void* p) {
    return (unsigned)__cvta_generic_to_shared(p);
}
__device__ __forceinline__ void cpasync16(unsigned s, const void* g) {
    asm volatile("cp.async.cg.shared.global [%0], [%1], 16;\n" :: "r"(s), "l"(g));
}
__device__ __forceinline__ void ldm_x4(unsigned a, unsigned& r0, unsigned& r1,
                                       unsigned& r2, unsigned& r3) {
    asm volatile("ldmatrix.sync.aligned.m8n8.x4.shared.b16 {%0,%1,%2,%3}, [%4];"
                 : "=r"(r0), "=r"(r1), "=r"(r2), "=r"(r3) : "r"(a));
}
__device__ __forceinline__ void ldm_x4t(unsigned a, unsigned& r0, unsigned& r1,
                                        unsigned& r2, unsigned& r3) {
    asm volatile("ldmatrix.sync.aligned.m8n8.x4.trans.shared.b16 {%0,%1,%2,%3}, [%4];"
                 : "=r"(r0), "=r"(r1), "=r"(r2), "=r"(r3) : "r"(a));
}
__device__ __forceinline__ void mma16816(float* c, const unsigned* a, const unsigned* b) {
    asm volatile(
        "mma.sync.aligned.m16n8k16.row.col.f32.f16.f16.f32 "
        "{%0,%1,%2,%3},{%4,%5,%6,%7},{%8,%9},{%0,%1,%2,%3};"
        : "+f"(c[0]), "+f"(c[1]), "+f"(c[2]), "+f"(c[3])
        : "r"(a[0]), "r"(a[1]), "r"(a[2]), "r"(a[3]), "r"(b[0]), "r"(b[1]));
}
__device__ __forceinline__ void split1(float v, __half& hi, __half& lo) {
    hi = __float2half(v);
    lo = __float2half(v - __half2float(hi));
}

// ---------------- bitmask pack + maxt reset ----------------
__global__ void pack_mask_k(const int* __restrict__ adj, unsigned* __restrict__ mask,
                            unsigned* __restrict__ keys) {
    int i = blockIdx.x;
    int w = threadIdx.x;
    if (i == 0 && w < 8) keys[w] = 0u;
    const int* row = adj + (size_t)i * NN + w * 32;
    unsigned bits = 0;
#pragma unroll
    for (int b = 0; b < 32; b++) bits |= (row[b] > 0 ? 1u : 0u) << b;
    mask[i * 128 + w] = bits;
}

// ---------------- fp32 GEMM for the small projections ----------------
template <int BN, int TN>
__global__ void __launch_bounds__(256) gemm128_k(
    const float* __restrict__ A, const float* __restrict__ B, float* __restrict__ C,
    int K, int lda, int ldb, int ldc,
    const float* __restrict__ bias, int act) {
    __shared__ float As[2][16][128];
    __shared__ float Bs[2][16][BN];
    const int tid = threadIdx.x;
    const int tx = tid & 15, ty = tid >> 4;
    const int row0 = blockIdx.y * 128, col0 = blockIdx.x * BN;
    int am[2], akq[2];
#pragma unroll
    for (int i = 0; i < 2; i++) {
        int idx = tid + i * 256;
        am[i] = idx >> 2;
        akq[i] = (idx & 3) << 2;
    }
    constexpr int BCNT = (16 * BN / 4) / 256;
    int bk[BCNT], bn[BCNT];
#pragma unroll
    for (int i = 0; i < BCNT; i++) {
        int idx = tid + i * 256;
        bk[i] = idx / (BN / 4);
        bn[i] = (idx % (BN / 4)) << 2;
    }
    float acc[8][TN];
#pragma unroll
    for (int i = 0; i < 8; i++)
#pragma unroll
        for (int j = 0; j < TN; j++) acc[i][j] = 0.f;
    float4 aR[2];
    float4 bR[BCNT];
#pragma unroll
    for (int i = 0; i < 2; i++)
        aR[i] = *(const float4*)(A + (size_t)(row0 + am[i]) * lda + akq[i]);
#pragma unroll
    for (int i = 0; i < BCNT; i++)
        bR[i] = *(const float4*)(B + (size_t)bk[i] * ldb + col0 + bn[i]);
#pragma unroll
    for (int i = 0; i < 2; i++) {
        As[0][akq[i] + 0][am[i]] = aR[i].x;
        As[0][akq[i] + 1][am[i]] = aR[i].y;
        As[0][akq[i] + 2][am[i]] = aR[i].z;
        As[0][akq[i] + 3][am[i]] = aR[i].w;
    }
#pragma unroll
    for (int i = 0; i < BCNT; i++) *(float4*)&Bs[0][bk[i]][bn[i]] = bR[i];
    __syncthreads();
    const int nT = K >> 4;
    for (int t = 0; t < nT; t++) {
        const int buf = t & 1;
        if (t + 1 < nT) {
            const int k0 = (t + 1) << 4;
#pragma unroll
            for (int i = 0; i < 2; i++)
                aR[i] = *(const float4*)(A + (size_t)(row0 + am[i]) * lda + k0 + akq[i]);
#pragma unroll
            for (int i = 0; i < BCNT; i++)
                bR[i] = *(const float4*)(B + (size_t)(k0 + bk[i]) * ldb + col0 + bn[i]);
        }
#pragma unroll
        for (int kk = 0; kk < 16; kk++) {
            float4 a0 = *(const float4*)&As[buf][kk][ty * 8];
            float4 a1 = *(const float4*)&As[buf][kk][ty * 8 + 4];
            float av[8] = {a0.x, a0.y, a0.z, a0.w, a1.x, a1.y, a1.z, a1.w};
            float bv[TN];
            float4 b0 = *(const float4*)&Bs[buf][kk][tx * TN];
            bv[0] = b0.x; bv[1] = b0.y; bv[2] = b0.z; bv[3] = b0.w;
            if (TN == 8) {
                float4 b1 = *(const float4*)&Bs[buf][kk][tx * TN + 4];
                bv[4] = b1.x; bv[5] = b1.y; bv[6] = b1.z; bv[7] = b1.w;
            }
#pragma unroll
            for (int i = 0; i < 8; i++)
#pragma unroll
                for (int j = 0; j < TN; j++) acc[i][j] += av[i] * bv[j];
        }
        if (t + 1 < nT) {
            const int nb = buf ^ 1;
#pragma unroll
            for (int i = 0; i < 2; i++) {
                As[nb][akq[i] + 0][am[i]] = aR[i].x;
                As[nb][akq[i] + 1][am[i]] = aR[i].y;
                As[nb][akq[i] + 2][am[i]] = aR[i].z;
                As[nb][akq[i] + 3][am[i]] = aR[i].w;
            }
#pragma unroll
            for (int i = 0; i < BCNT; i++) *(float4*)&Bs[nb][bk[i]][bn[i]] = bR[i];
            __syncthreads();
        }
    }
#pragma unroll
    for (int i = 0; i < 8; i++) {
        int row = row0 + ty * 8 + i;
#pragma unroll
        for (int j4 = 0; j4 < TN; j4 += 4) {
            float r[4];
#pragma unroll
            for (int j = 0; j < 4; j++) {
                float x = acc[i][j4 + j];
                if (bias) x += bias[col0 + tx * TN + j4 + j];
                if (act == 1) x = fmaxf(x, 0.f);
                r[j] = x;
            }
            *(float4*)(C + (size_t)row * ldc + col0 + tx * TN + j4) =
                make_float4(r[0], r[1], r[2], r[3]);
        }
    }
}

// ---------------- fp16 tensor-core GEMM, 4-stage pipeline, 2 CTAs/SM ----------------
// TERMS=3: A split hi/lo, C = AhBh + AlBh + AhBl (projections, 22-bit A/B)
// TERMS=2: A single plane, C = A*Bh + A*Bl (P@h; P is fp16-exact-bounded)
template <int MT, int TERMS>
__global__ void __launch_bounds__(256, 2) mma3_k(
    const __half* __restrict__ Ahi, const __half* __restrict__ Alo,
    const __half* __restrict__ Bhi, const __half* __restrict__ Blo,
    float* __restrict__ C, __half* __restrict__ Chi, __half* __restrict__ Clo,
    int K, int lda, int ldb, int ldc,
    const float* __restrict__ rowScale, int act,
    long strideAz, long strideBz, long strideCz, int rsStride) {
    constexpr int BM = MT * 32;
    constexpr int ABYTES = BM * 128;       // padded to 128B/row even for TERMS=2
    constexpr int BBYTES = 32 * 512;
    constexpr int LA = (TERMS == 3) ? (BM / 32) : (BM / 64);  // 256-thread chunks

    extern __shared__ __align__(16) char smraw[];
    unsigned aBase = sptr(smraw);
    unsigned bBase = aBase + 4 * ABYTES;

    const int z = blockIdx.z;
    Ahi += (long)z * strideAz;
    if (TERMS == 3) Alo += (long)z * strideAz;
    Bhi += (long)z * strideBz;
    Blo += (long)z * strideBz;
    long cz = (long)z * strideCz;
    const int rs0 = z * rsStride;

    const int tid = threadIdx.x;
    const int w = tid >> 5, lane = tid & 31;
    const int wm = w >> 2, wn = w & 3;
    const int row0 = blockIdx.y * BM, col0 = blockIdx.x * 128;
    const int nT = K >> 5;

    auto loadTile = [&](int buf, int k0) {
        if (TERMS == 3) {
#pragma unroll
            for (int i = 0; i < LA; i++) {
                int idx = i * 256 + tid;
                int plane = idx >= BM * 4 ? 1 : 0;
                int ii = idx - plane * BM * 4;
                int r = ii >> 2, c4 = ii & 3;
                const __half* g =
                    (plane ? Alo : Ahi) + (size_t)(row0 + r) * lda + k0 + c4 * 8;
                int c = c4 + plane * 4;
                cpasync16(aBase + buf * ABYTES + r * 128 + ((c ^ (r & 7)) << 4), g);
            }
        } else {
#pragma unroll
            for (int i = 0; i < LA; i++) {
                int idx = i * 256 + tid;              // 0 .. BM*4-1
                int r = idx >> 2, c4 = idx & 3;
                const __half* g = Ahi + (size_t)(row0 + r) * lda + k0 + c4 * 8;
                cpasync16(aBase + buf * ABYTES + r * 128 + ((c4 ^ (r & 7)) << 4), g);
            }
        }
#pragma unroll
        for (int i = 0; i < 4; i++) {
            int idx = i * 256 + tid;
            int plane = idx >> 9;
            int ii = idx & 511;
            int k = ii >> 4, c16 = ii & 15;
            const __half* g =
                (plane ? Blo : Bhi) + (size_t)(k0 + k) * ldb + col0 + c16 * 8;
            int c = c16 + plane * 16;
            int p = (c & 24) | ((c ^ k) & 7);
            cpasync16(bBase + buf * BBYTES + k * 512 + (p << 4), g);
        }
    };

    float acc[MT][4][4];
#pragma unroll
    for (int m = 0; m < MT; m++)
#pragma unroll
        for (int n = 0; n < 4; n++)
#pragma unroll
            for (int q = 0; q < 4; q++) acc[m][n][q] = 0.f;

    loadTile(0, 0);
    asm volatile("cp.async.commit_group;\n" ::);
    loadTile(1, 32);
    asm volatile("cp.async.commit_group;\n" ::);
    loadTile(2, 64);
    asm volatile("cp.async.commit_group;\n" ::);

    for (int t = 0; t < nT; t++) {
        asm volatile("cp.async.wait_group 2;\n" ::);
        __syncthreads();
        if (t + 3 < nT) {
            loadTile((t + 3) & 3, (t + 3) * 32);
        }
        asm volatile("cp.async.commit_group;\n" ::);

        const int buf = t & 3;
#pragma unroll
        for (int ks = 0; ks < 2; ks++) {
            unsigned ah[MT][4], al[MT][4], bh[4][2], bl[4][2];
#pragma unroll
            for (int mt = 0; mt < MT; mt++) {
                int rA = wm * MT * 16 + mt * 16 + (lane & 15);
                int ck = ks * 2 + (lane >> 4);
                unsigned base = aBase + buf * ABYTES + rA * 128;
                ldm_x4(base + ((ck ^ (rA & 7)) << 4),
                       ah[mt][0], ah[mt][1], ah[mt][2], ah[mt][3]);
                if (TERMS == 3)
                    ldm_x4(base + (((ck + 4) ^ (rA & 7)) << 4),
                           al[mt][0], al[mt][1], al[mt][2], al[mt][3]);
            }
#pragma unroll
            for (int np = 0; np < 2; np++) {
                int kr = ks * 16 + (lane & 15);
                int cb = wn * 4 + np * 2 + (lane >> 4);
                unsigned base = bBase + buf * BBYTES + kr * 512;
                int ph = (cb & 24) | ((cb ^ kr) & 7);
                ldm_x4t(base + (ph << 4), bh[2 * np][0], bh[2 * np][1],
                        bh[2 * np + 1][0], bh[2 * np + 1][1]);
                int cl = cb + 16;
                int pl = (cl & 24) | ((cl ^ kr) & 7);
                ldm_x4t(base + (pl << 4), bl[2 * np][0], bl[2 * np][1],
                        bl[2 * np + 1][0], bl[2 * np + 1][1]);
            }
#pragma unroll
            for (int mt = 0; mt < MT; mt++)
#pragma unroll
                for (int nt = 0; nt < 4; nt++) {
                    mma16816(acc[mt][nt], ah[mt], bh[nt]);
                    if (TERMS == 3) mma16816(acc[mt][nt], al[mt], bh[nt]);
                    mma16816(acc[mt][nt], ah[mt], bl[nt]);
                }
        }
    }

#pragma unroll
    for (int mt = 0; mt < MT; mt++) {
        int r1 = row0 + wm * MT * 16 + mt * 16 + (lane >> 2);
        int r2 = r1 + 8;
        float s1 = rowScale ? rowScale[rs0 + r1] : 1.f;
        float s2 = rowScale ? rowScale[rs0 + r2] : 1.f;
#pragma unroll
        for (int nt = 0; nt < 4; nt++) {
            int cidx = col0 + wn * 32 + nt * 8 + (lane & 3) * 2;
            float v0 = acc[mt][nt][0] * s1, v1 = acc[mt][nt][1] * s1;
            float v2 = acc[mt][nt][2] * s2, v3 = acc[mt][nt][3] * s2;
            if (act == 1) {
                v0 = fmaxf(v0, 0.f); v1 = fmaxf(v1, 0.f);
                v2 = fmaxf(v2, 0.f); v3 = fmaxf(v3, 0.f);
            }
            if (C) {
                *(float2*)(C + cz + (size_t)r1 * ldc + cidx) = make_float2(v0, v1);
                *(float2*)(C + cz + (size_t)r2 * ldc + cidx) = make_float2(v2, v3);
            }
            if (Chi) {
                __half2 h, l;
                split1(v0, h.x, l.x); split1(v1, h.y, l.y);
                *(__half2*)(Chi + cz + (size_t)r1 * ldc + cidx) = h;
                *(__half2*)(Clo + cz + (size_t)r1 * ldc + cidx) = l;
                split1(v2, h.x, l.x); split1(v3, h.y, l.y);
                *(__half2*)(Chi + cz + (size_t)r2 * ldc + cidx) = h;
                *(__half2*)(Clo + cz + (size_t)r2 * ldc + cidx) = l;
            }
        }
    }
}

// ---------------- split fp32 -> fp16 hi/lo planes ----------------
__global__ void split_k(const float* __restrict__ x, __half* __restrict__ hi,
                        __half* __restrict__ lo, int n) {
    int i = blockIdx.x * 256 + threadIdx.x;
    if (i < n) {
        __half h, l;
        split1(x[i], h, l);
        hi[i] = h; lo[i] = l;
    }
}

// ---------------- s,t from fp32 h: warp per row, 8 rows/block ----------------
__global__ void __launch_bounds__(256) st8_k(
    const float* __restrict__ h, long hStride,
    const float* __restrict__ a, long aStride, int F,
    float* __restrict__ s, float* __restrict__ t,
    unsigned* __restrict__ key) {
    int b = blockIdx.y;
    h += (long)b * hStride;
    a += (long)b * aStride;
    int w = threadIdx.x >> 5, lane = threadIdx.x & 31;
    int row = blockIdx.x * 8 + w;
    const float* hr = h + (size_t)row * F;
    float as = 0.f, at = 0.f;
    for (int k = lane * 4; k < F; k += 128) {
        float4 v = *(const float4*)(hr + k);
        float4 a0 = *(const float4*)(a + k);
        float4 a1 = *(const float4*)(a + F + k);
        as += v.x * a0.x + v.y * a0.y + v.z * a0.z + v.w * a0.w;
        at += v.x * a1.x + v.y * a1.y + v.z * a1.z + v.w * a1.w;
    }
#pragma unroll
    for (int o = 16; o > 0; o >>= 1) {
        as += __shfl_xor_sync(0xffffffffu, as, o);
        at += __shfl_xor_sync(0xffffffffu, at, o);
    }
    if (lane == 0) {
        s[b * NN + row] = as;
        t[b * NN + row] = at;
        atomicMax(&key[b], fenc(at));
    }
}

// ---------------- s,t from fp16 hi/lo planes: warp per row, 8 rows/block ----------------
__global__ void __launch_bounds__(256) st8hl_k(
    const __half* __restrict__ hhi, const __half* __restrict__ hlo,
    long hStride, const float* __restrict__ a, long aStride, int F,
    float* __restrict__ s, float* __restrict__ t,
    unsigned* __restrict__ key) {
    int b = blockIdx.y;
    hhi += (long)b * hStride;
    hlo += (long)b * hStride;
    a += (long)b * aStride;
    int w = threadIdx.x >> 5, lane = threadIdx.x & 31;
    int row = blockIdx.x * 8 + w;
    const __half* hr = hhi + (size_t)row * F;
    const __half* lr = hlo + (size_t)row * F;
    float as = 0.f, at = 0.f;
    for (int k = lane * 8; k < F; k += 256) {
        uint4 hv = *(const uint4*)(hr + k);
        uint4 lv = *(const uint4*)(lr + k);
        const __half* hb = (const __half*)&hv;
        const __half* lb = (const __half*)&lv;
#pragma unroll
        for (int q = 0; q < 8; q++) {
            float v = __half2float(hb[q]) + __half2float(lb[q]);
            as += v * a[k + q];
            at += v * a[F + k + q];
        }
    }
#pragma unroll
    for (int o = 16; o > 0; o >>= 1) {
        as += __shfl_xor_sync(0xffffffffu, as, o);
        at += __shfl_xor_sync(0xffffffffu, at, o);
    }
    if (lane == 0) {
        s[b * NN + row] = as;
        t[b * NN + row] = at;
        atomicMax(&key[b], fenc(at));
    }
}

__global__ void etf_k(const float* __restrict__ t, const unsigned* __restrict__ key,
                      float* __restrict__ maxt, float* __restrict__ E,
                      float* __restrict__ Fv) {
    int b = blockIdx.y;
    float mt = fdec(key[b]);
    if (blockIdx.x == 0 && threadIdx.x == 0) maxt[b] = mt;
    int j = blockIdx.x * 512 + threadIdx.x;
    float tv = t[b * NN + j] - mt;
    E[b * NN + j] = expf(tv);
    Fv[b * NN + j] = expf(0.2f * tv);
}

// ---------------- per-row masked softmax weights -> single fp16 plane, z-batched ----
__global__ void __launch_bounds__(256) attn8_k(
    const float* __restrict__ s, const float* __restrict__ E,
    const float* __restrict__ Fv, const float* __restrict__ maxt,
    const unsigned* __restrict__ mask,
    __half* __restrict__ Pf, float* __restrict__ invZ) {
    __shared__ float shE[NN];
    __shared__ float shF[NN];
    const int z = blockIdx.y;
    s += (size_t)z * NN;
    E += (size_t)z * NN;
    Fv += (size_t)z * NN;
    Pf += (size_t)z * NN * NN;
    invZ += (size_t)z * NN;

    int tid = threadIdx.x;
#pragma unroll
    for (int j = 0; j < 4; j++) {
        ((float4*)shE)[j * 256 + tid] = ((const float4*)E)[j * 256 + tid];
        ((float4*)shF)[j * 256 + tid] = ((const float4*)Fv)[j * 256 + tid];
    }
    __syncthreads();

    const int w = tid >> 5, lane = tid & 31;
    const int row = blockIdx.x * 8 + w;
    float q = s[row] + maxt[z];
    float m = fmaxf(q, 0.2f * q);
    float c = expf(q - m);
    float d = expf(0.2f * q - m);

    const unsigned* mrow = mask + (size_t)row * 128;
    __half* PRow = Pf + (size_t)row * NN;

    float sum = 0.f;
#pragma unroll
    for (int it = 0; it < 16; it++) {
        int j0 = it * 256 + lane * 8;
        unsigned mbyte = (mrow[j0 >> 5] >> (j0 & 31)) & 0xFFu;
        float4 e0 = ((const float4*)shE)[j0 >> 2];
        float4 e1 = ((const float4*)shE)[(j0 >> 2) + 1];
        float4 f0 = ((const float4*)shF)[j0 >> 2];
        float4 f1 = ((const float4*)shF)[(j0 >> 2) + 1];
        float e[8] = {e0.x, e0.y, e0.z, e0.w, e1.x, e1.y, e1.z, e1.w};
        float f[8] = {f0.x, f0.y, f0.z, f0.w, f1.x, f1.y, f1.z, f1.w};
        __half pb[8];
#pragma unroll
        for (int k = 0; k < 8; k++) {
            float p = ((mbyte >> k) & 1u) ? fmaxf(c * e[k], d * f[k]) : 0.f;
            sum += p;
            pb[k] = __float2half(p);
        }
        *(uint4*)(PRow + j0) = *(const uint4*)pb;
    }
#pragma unroll
    for (int o = 16; o > 0; o >>= 1) sum += __shfl_xor_sync(0xffffffffu, sum, o);
    if (lane == 0) invZ[row] = 1.f / sum;
}

// ---------------- GroupNorm ----------------
__global__ void gn_reduce1_k(const float* __restrict__ h, float* __restrict__ part) {
    __shared__ float r1[256], r2[256];
    int tid = threadIdx.x;
    float s = 0.f, q = 0.f;
    for (size_t idx = (size_t)blockIdx.x * 256 + tid; idx < (size_t)NN * 1536;
         idx += (size_t)2048 * 256) {
        float v = h[idx];
        s += v;
        q += v * v;
    }
    r1[tid] = s; r2[tid] = q;
    __syncthreads();
    for (int s2 = 128; s2 > 0; s2 >>= 1) {
        if (tid < s2) { r1[tid] += r1[tid + s2]; r2[tid] += r2[tid + s2]; }
        __syncthreads();
    }
    if (tid == 0) { part[blockIdx.x] = r1[0]; part[2048 + blockIdx.x] = r2[0]; }
}

__global__ void gn_reduce2_k(const float* __restrict__ part, float* __restrict__ stats) {
    __shared__ double r1[1024], r2[1024];
    int tid = threadIdx.x;
    double s = 0.0, q = 0.0;
    for (int i = tid; i < 2048; i += 1024) { s += part[i]; q += part[2048 + i]; }
    r1[tid] = s; r2[tid] = q;
    __syncthreads();
    for (int s2 = 512; s2 > 0; s2 >>= 1) {
        if (tid < s2) { r1[tid] += r1[tid + s2]; r2[tid] += r2[tid + s2]; }
        __syncthreads();
    }
    if (tid == 0) {
        double n = (double)NN * 1536.0;
        double mu = r1[0] / n;
        double var = (r2[0] - n * mu * mu) / (n - 1.0);
        stats[0] = (float)mu;
        stats[1] = (float)(1.0 / sqrt(var + 1e-5));
    }
}

__global__ void gn_apply_k(const float* __restrict__ h, const float* __restrict__ w,
                           const float* __restrict__ b, const float* __restrict__ stats,
                           __half* __restrict__ hi, __half* __restrict__ lo) {
    size_t idx = (size_t)blockIdx.x * 256 + threadIdx.x;
    if (idx < (size_t)NN * 1536) {
        int c = (int)(idx % 1536);
        float v = (h[idx] - stats[0]) * stats[1] * w[c] + b[c];
        __half hh, ll;
        split1(v, hh, ll);
        hi[idx] = hh; lo[idx] = ll;
    }
}

// ---------------- host ----------------
extern "C" void kernel_launch(void* const* d_in, const int* in_sizes, int n_in,
                              void* d_out, int out_size) {
    const float* x       = (const float*)d_in[0];
    const int*   adj     = (const int*)d_in[1];
    const float* lin1_w  = (const float*)d_in[2];
    const float* lin1_b  = (const float*)d_in[3];
    const float* lin2_w  = (const float*)d_in[4];
    const float* lin2_b  = (const float*)d_in[5];
    const float* conv1_W = (const float*)d_in[6];
    const float* conv1_a = (const float*)d_in[7];
    const float* att_W   = (const float*)d_in[8];
    const float* att_a   = (const float*)d_in[9];
    const float* gn_w    = (const float*)d_in[10];
    const float* gn_b    = (const float*)d_in[11];
    const float* conv2_W = (const float*)d_in[12];
    const float* conv2_a = (const float*)d_in[13];
    float* out = (float*)d_out;

    void* p;
    cudaGetSymbolAddress(&p, g_Pf);     __half* Pf = (__half*)p;
    cudaGetSymbolAddress(&p, g_hA);     float* hA = (float*)p;
    cudaGetSymbolAddress(&p, g_hAhi);   __half* hAhi = (__half*)p;
    cudaGetSymbolAddress(&p, g_hAlo);   __half* hAlo = (__half*)p;
    cudaGetSymbolAddress(&p, g_out1hi); __half* out1hi = (__half*)p;
    cudaGetSymbolAddress(&p, g_out1lo); __half* out1lo = (__half*)p;
    cudaGetSymbolAddress(&p, g_cat);    float* cat = (float*)p;
    cudaGetSymbolAddress(&p, g_cathi);  __half* cathi = (__half*)p;
    cudaGetSymbolAddress(&p, g_catlo);  __half* catlo = (__half*)p;
    cudaGetSymbolAddress(&p, g_hB6hi);  __half* hB6hi = (__half*)p;
    cudaGetSymbolAddress(&p, g_hB6lo);  __half* hB6lo = (__half*)p;
    cudaGetSymbolAddress(&p, g_hBhi);   __half* hBhi = (__half*)p;
    cudaGetSymbolAddress(&p, g_hBlo);   __half* hBlo = (__half*)p;
    cudaGetSymbolAddress(&p, g_attWhi); __half* attWhi = (__half*)p;
    cudaGetSymbolAddress(&p, g_attWlo); __half* attWlo = (__half*)p;
    cudaGetSymbolAddress(&p, g_c2Whi);  __half* c2Whi = (__half*)p;
    cudaGetSymbolAddress(&p, g_c2Wlo);  __half* c2Wlo = (__half*)p;
    cudaGetSymbolAddress(&p, g_l1);     float* l1 = (float*)p;
    cudaGetSymbolAddress(&p, g_l2);     float* l2 = (float*)p;
    cudaGetSymbolAddress(&p, g_sv);     float* sv = (float*)p;
    cudaGetSymbolAddress(&p, g_tv);     float* tv = (float*)p;
    cudaGetSymbolAddress(&p, g_E);      float* E = (float*)p;
    cudaGetSymbolAddress(&p, g_Fv);     float* Fv = (float*)p;
    cudaGetSymbolAddress(&p, g_maxtKey);unsigned* keys = (unsigned*)p;
    cudaGetSymbolAddress(&p, g_maxt);   float* maxt = (float*)p;
    cudaGetSymbolAddress(&p, g_invZ);   float* invZ = (float*)p;
    cudaGetSymbolAddress(&p, g_mask);   unsigned* mask = (unsigned*)p;
    cudaGetSymbolAddress(&p, g_part);   float* part = (float*)p;
    cudaGetSymbolAddress(&p, g_stats);  float* stats = (float*)p;

    cudaFuncSetAttribute(mma3_k<2, 2>, cudaFuncAttributeMaxDynamicSharedMemorySize, 98304);
    cudaFuncSetAttribute(mma3_k<2, 3>, cudaFuncAttributeMaxDynamicSharedMemorySize, 98304);

    pack_mask_k<<<NN, 128>>>(adj, mask, keys);

    // lin1 + lin2 + conv1 projection (fp32)
    gemm128_k<64, 4><<<dim3(1, 32), 256>>>(x,  lin1_w, l1, 128, 128, 64, 64, lin1_b, 0);
    gemm128_k<64, 4><<<dim3(1, 32), 256>>>(l1, lin2_w, l2, 64, 64, 64, 64, lin2_b, 0);
    gemm128_k<128, 8><<<dim3(4, 32), 256>>>(l2, conv1_W, hA, 64, 64, 512, 512, nullptr, 0);
    split_k<<<(NN * 512 + 255) / 256, 256>>>(hA, hAhi, hAlo, NN * 512);

    split_k<<<(6 * 512 * 256 + 255) / 256, 256>>>(att_W, attWhi, attWlo, 6 * 512 * 256);
    split_k<<<(1536 * 256 + 255) / 256, 256>>>(conv2_W, c2Whi, c2Wlo, 1536 * 256);

    // ---- GAT conv1 (F=512): P slot 0, invZ slot 0 ----
    st8_k<<<dim3(512, 1), 256>>>(hA, 0, conv1_a, 0, 512, sv, tv, keys);
    etf_k<<<dim3(8, 1), 512>>>(tv, keys, maxt, E, Fv);
    attn8_k<<<dim3(512, 1), 256>>>(sv, E, Fv, maxt, mask, Pf, invZ);
    mma3_k<2, 2><<<dim3(4, 64, 1), 256, 98304>>>(Pf, nullptr, hAhi, hAlo,
                                                 nullptr, out1hi, out1lo,
                                                 NN, NN, 512, 512, invZ, 1,
                                                 0, 0, 0, 0);

    // ---- 6 head projections, batched (fp16 planes) ----
    mma3_k<2, 3><<<dim3(2, 64, 6), 256, 98304>>>(out1hi, out1lo, attWhi, attWlo,
                                                 nullptr, hB6hi, hB6lo,
                                                 512, 512, 256, 256, nullptr, 0,
                                                 0, (long)512 * 256, (long)NN * 256, 0);
    st8hl_k<<<dim3(512, 6), 256>>>(hB6hi, hB6lo, (long)NN * 256, att_a, 512, 256,
                                   sv + NN, tv + NN, keys + 1);
    etf_k<<<dim3(8, 6), 512>>>(tv + NN, keys + 1, maxt + 1, E + NN, Fv + NN);
    attn8_k<<<dim3(512, 6), 256>>>(sv + NN, E + NN, Fv + NN, maxt + 1, mask, Pf, invZ);
    mma3_k<2, 2><<<dim3(2, 64, 6), 256, 98304>>>(Pf, nullptr, hB6hi, hB6lo,
                                                 cat, nullptr, nullptr,
                                                 NN, NN, 256, 1536, invZ, 1,
                                                 (long)NN * NN, (long)NN * 256, 256, NN);

    // ---- GroupNorm ----
    gn_reduce1_k<<<2048, 256>>>(cat, part);
    gn_reduce2_k<<<1, 1024>>>(part, stats);
    gn_apply_k<<<(int)(((size_t)NN * 1536 + 255) / 256), 256>>>(cat, gn_w, gn_b, stats,
                                                                cathi, catlo);

    // ---- GAT conv2 (F=256): P slot 0, invZ slot 0, data slot 7 ----
    mma3_k<2, 3><<<dim3(2, 64, 1), 256, 98304>>>(cathi, catlo, c2Whi, c2Wlo,
                                                 nullptr, hBhi, hBlo,
                                                 1536, 1536, 256, 256, nullptr, 0,
                                                 0, 0, 0, 0);
    st8hl_k<<<dim3(512, 1), 256>>>(hBhi, hBlo, 0, conv2_a, 0, 256,
                                   sv + 7 * NN, tv + 7 * NN, keys + 7);
    etf_k<<<dim3(8, 1), 512>>>(tv + 7 * NN, keys + 7, maxt + 7, E + 7 * NN, Fv + 7 * NN);
    attn8_k<<<dim3(512, 1), 256>>>(sv + 7 * NN, E + 7 * NN, Fv + 7 * NN, maxt + 7, mask,
                                   Pf, invZ);
    mma3_k<2, 2><<<dim3(2, 64, 1), 256, 98304>>>(Pf, nullptr, hBhi, hBlo,
                                                 out, nullptr, nullptr,
                                                 NN, NN, 256, 256, invZ, 0,
                                                 0, 0, 0, 0);
}

// round 16
// speedup vs baseline: 1.8535x; 1.3665x over previous
#include <cuda_runtime.h>
#include <cuda_fp16.h>
#include <cstdint>
#include <math.h>

#define NN 4096

// ---------------- scratch (device globals) ----------------
__device__ __half g_Pf[6ULL * NN * NN];          // 6 P slots, single fp16 plane
__device__ float g_hA[NN * 512];
__device__ __half g_hAhi[NN * 512];
__device__ __half g_hAlo[NN * 512];
__device__ __half g_out1hi[NN * 512];
__device__ __half g_out1lo[NN * 512];
__device__ float g_cat[NN * 1536];
__device__ __half g_cathi[NN * 1536];
__device__ __half g_catlo[NN * 1536];
__device__ __half g_hB6hi[6 * NN * 256];
__device__ __half g_hB6lo[6 * NN * 256];
__device__ __half g_hBhi[NN * 256];
__device__ __half g_hBlo[NN * 256];
__device__ __half g_attWhi[6 * 512 * 256];
__device__ __half g_attWlo[6 * 512 * 256];
__device__ __half g_c2Whi[1536 * 256];
__device__ __half g_c2Wlo[1536 * 256];
__device__ float g_l1[NN * 64];
__device__ float g_l2[NN * 64];
__device__ float g_sv[8 * NN];
__device__ float g_tv[8 * NN];
__device__ float g_E[8 * NN];
__device__ float g_Fv[8 * NN];
__device__ unsigned g_maxtKey[8];
__device__ float g_maxt[8];
__device__ float g_invZ[8 * NN];
__device__ unsigned g_mask[NN * 128];
__device__ float g_part[2 * 2048];
__device__ float g_stats[2];

__device__ __forceinline__ unsigned fenc(float f) {
    unsigned u = __float_as_uint(f);
    return (u & 0x80000000u) ? ~u : (u | 0x80000000u);
}
__device__ __forceinline__ float fdec(unsigned k) {
    unsigned u = (k & 0x80000000u) ? (k & 0x7fffffffu) : ~k;
    return __uint_as_float(u);
}
__device__ __forceinline__ unsigned sptr(const void* p) {
    return (unsigned)__cvta_generic_to_shared(p);
}
__device__ __forceinline__ void cpasync16(unsigned s, const void* g) {
    asm volatile("cp.async.cg.shared.global [%0], [%1], 16;\n" :: "r"(s), "l"(g));
}
__device__ __forceinline__ void ldm_x4(unsigned a, unsigned& r0, unsigned& r1,
                                       unsigned& r2, unsigned& r3) {
    asm volatile("ldmatrix.sync.aligned.m8n8.x4.shared.b16 {%0,%1,%2,%3}, [%4];"
                 : "=r"(r0), "=r"(r1), "=r"(r2), "=r"(r3) : "r"(a));
}
__device__ __forceinline__ void ldm_x4t(unsigned a, unsigned& r0, unsigned& r1,
                                        unsigned& r2, unsigned& r3) {
    asm volatile("ldmatrix.sync.aligned.m8n8.x4.trans.shared.b16 {%0,%1,%2,%3}, [%4];"
                 : "=r"(r0), "=r"(r1), "=r"(r2), "=r"(r3) : "r"(a));
}
__device__ __forceinline__ void mma16816(float* c, const unsigned* a, const unsigned* b) {
    asm volatile(
        "mma.sync.aligned.m16n8k16.row.col.f32.f16.f16.f32 "
        "{%0,%1,%2,%3},{%4,%5,%6,%7},{%8,%9},{%0,%1,%2,%3};"
        : "+f"(c[0]), "+f"(c[1]), "+f"(c[2]), "+f"(c[3])
        : "r"(a[0]), "r"(a[1]), "r"(a[2]), "r"(a[3]), "r"(b[0]), "r"(b[1]));
}
__device__ __forceinline__ void split1(float v, __half& hi, __half& lo) {
    hi = __float2half(v);
    lo = __float2half(v - __half2float(hi));
}

// ---------------- bitmask pack + maxt reset ----------------
__global__ void pack_mask_k(const int* __restrict__ adj, unsigned* __restrict__ mask,
                            unsigned* __restrict__ keys) {
    int i = blockIdx.x;
    int w = threadIdx.x;
    if (i == 0 && w < 8) keys[w] = 0u;
    const int* row = adj + (size_t)i * NN + w * 32;
    unsigned bits = 0;
#pragma unroll
    for (int b = 0; b < 32; b++) bits |= (row[b] > 0 ? 1u : 0u) << b;
    mask[i * 128 + w] = bits;
}

// ---------------- fp32 GEMM for the small projections ----------------
template <int BN, int TN>
__global__ void __launch_bounds__(256) gemm128_k(
    const float* __restrict__ A, const float* __restrict__ B, float* __restrict__ C,
    int K, int lda, int ldb, int ldc,
    const float* __restrict__ bias, int act) {
    __shared__ float As[2][16][128];
    __shared__ float Bs[2][16][BN];
    const int tid = threadIdx.x;
    const int tx = tid & 15, ty = tid >> 4;
    const int row0 = blockIdx.y * 128, col0 = blockIdx.x * BN;
    int am[2], akq[2];
#pragma unroll
    for (int i = 0; i < 2; i++) {
        int idx = tid + i * 256;
        am[i] = idx >> 2;
        akq[i] = (idx & 3) << 2;
    }
    constexpr int BCNT = (16 * BN / 4) / 256;
    int bk[BCNT], bn[BCNT];
#pragma unroll
    for (int i = 0; i < BCNT; i++) {
        int idx = tid + i * 256;
        bk[i] = idx / (BN / 4);
        bn[i] = (idx % (BN / 4)) << 2;
    }
    float acc[8][TN];
#pragma unroll
    for (int i = 0; i < 8; i++)
#pragma unroll
        for (int j = 0; j < TN; j++) acc[i][j] = 0.f;
    float4 aR[2];
    float4 bR[BCNT];
#pragma unroll
    for (int i = 0; i < 2; i++)
        aR[i] = *(const float4*)(A + (size_t)(row0 + am[i]) * lda + akq[i]);
#pragma unroll
    for (int i = 0; i < BCNT; i++)
        bR[i] = *(const float4*)(B + (size_t)bk[i] * ldb + col0 + bn[i]);
#pragma unroll
    for (int i = 0; i < 2; i++) {
        As[0][akq[i] + 0][am[i]] = aR[i].x;
        As[0][akq[i] + 1][am[i]] = aR[i].y;
        As[0][akq[i] + 2][am[i]] = aR[i].z;
        As[0][akq[i] + 3][am[i]] = aR[i].w;
    }
#pragma unroll
    for (int i = 0; i < BCNT; i++) *(float4*)&Bs[0][bk[i]][bn[i]] = bR[i];
    __syncthreads();
    const int nT = K >> 4;
    for (int t = 0; t < nT; t++) {
        const int buf = t & 1;
        if (t + 1 < nT) {
            const int k0 = (t + 1) << 4;
#pragma unroll
            for (int i = 0; i < 2; i++)
                aR[i] = *(const float4*)(A + (size_t)(row0 + am[i]) * lda + k0 + akq[i]);
#pragma unroll
            for (int i = 0; i < BCNT; i++)
                bR[i] = *(const float4*)(B + (size_t)(k0 + bk[i]) * ldb + col0 + bn[i]);
        }
#pragma unroll
        for (int kk = 0; kk < 16; kk++) {
            float4 a0 = *(const float4*)&As[buf][kk][ty * 8];
            float4 a1 = *(const float4*)&As[buf][kk][ty * 8 + 4];
            float av[8] = {a0.x, a0.y, a0.z, a0.w, a1.x, a1.y, a1.z, a1.w};
            float bv[TN];
            float4 b0 = *(const float4*)&Bs[buf][kk][tx * TN];
            bv[0] = b0.x; bv[1] = b0.y; bv[2] = b0.z; bv[3] = b0.w;
            if (TN == 8) {
                float4 b1 = *(const float4*)&Bs[buf][kk][tx * TN + 4];
                bv[4] = b1.x; bv[5] = b1.y; bv[6] = b1.z; bv[7] = b1.w;
            }
#pragma unroll
            for (int i = 0; i < 8; i++)
#pragma unroll
                for (int j = 0; j < TN; j++) acc[i][j] += av[i] * bv[j];
        }
        if (t + 1 < nT) {
            const int nb = buf ^ 1;
#pragma unroll
            for (int i = 0; i < 2; i++) {
                As[nb][akq[i] + 0][am[i]] = aR[i].x;
                As[nb][akq[i] + 1][am[i]] = aR[i].y;
                As[nb][akq[i] + 2][am[i]] = aR[i].z;
                As[nb][akq[i] + 3][am[i]] = aR[i].w;
            }
#pragma unroll
            for (int i = 0; i < BCNT; i++) *(float4*)&Bs[nb][bk[i]][bn[i]] = bR[i];
            __syncthreads();
        }
    }
#pragma unroll
    for (int i = 0; i < 8; i++) {
        int row = row0 + ty * 8 + i;
#pragma unroll
        for (int j4 = 0; j4 < TN; j4 += 4) {
            float r[4];
#pragma unroll
            for (int j = 0; j < 4; j++) {
                float x = acc[i][j4 + j];
                if (bias) x += bias[col0 + tx * TN + j4 + j];
                if (act == 1) x = fmaxf(x, 0.f);
                r[j] = x;
            }
            *(float4*)(C + (size_t)row * ldc + col0 + tx * TN + j4) =
                make_float4(r[0], r[1], r[2], r[3]);
        }
    }
}

// ---------------- fp16 tensor-core GEMM, 4-stage pipeline, 2 CTAs/SM ----------------
// TERMS=3: A split hi/lo, B split hi/lo: C = AhBh + AlBh + AhBl (projections)
// TERMS=1: single planes both sides:     C = A*Bh              (P@h)
template <int MT, int TERMS>
__global__ void __launch_bounds__(256, 2) mma3_k(
    const __half* __restrict__ Ahi, const __half* __restrict__ Alo,
    const __half* __restrict__ Bhi, const __half* __restrict__ Blo,
    float* __restrict__ C, __half* __restrict__ Chi, __half* __restrict__ Clo,
    int K, int lda, int ldb, int ldc,
    const float* __restrict__ rowScale, int act,
    long strideAz, long strideBz, long strideCz, int rsStride) {
    constexpr int BM = MT * 32;
    constexpr int ABYTES = BM * 128;
    constexpr int BBYTES = 32 * 512;
    constexpr int LA = (TERMS == 3) ? (BM / 32) : (BM / 64);
    constexpr int LB = (TERMS == 3) ? 4 : 2;    // B-chunk iterations (hi+lo vs hi only)

    extern __shared__ __align__(16) char smraw[];
    unsigned aBase = sptr(smraw);
    unsigned bBase = aBase + 4 * ABYTES;

    const int z = blockIdx.z;
    Ahi += (long)z * strideAz;
    if (TERMS == 3) Alo += (long)z * strideAz;
    Bhi += (long)z * strideBz;
    if (TERMS == 3) Blo += (long)z * strideBz;
    long cz = (long)z * strideCz;
    const int rs0 = z * rsStride;

    const int tid = threadIdx.x;
    const int w = tid >> 5, lane = tid & 31;
    const int wm = w >> 2, wn = w & 3;
    const int row0 = blockIdx.y * BM, col0 = blockIdx.x * 128;
    const int nT = K >> 5;

    auto loadTile = [&](int buf, int k0) {
        if (TERMS == 3) {
#pragma unroll
            for (int i = 0; i < LA; i++) {
                int idx = i * 256 + tid;
                int plane = idx >= BM * 4 ? 1 : 0;
                int ii = idx - plane * BM * 4;
                int r = ii >> 2, c4 = ii & 3;
                const __half* g =
                    (plane ? Alo : Ahi) + (size_t)(row0 + r) * lda + k0 + c4 * 8;
                int c = c4 + plane * 4;
                cpasync16(aBase + buf * ABYTES + r * 128 + ((c ^ (r & 7)) << 4), g);
            }
        } else {
#pragma unroll
            for (int i = 0; i < LA; i++) {
                int idx = i * 256 + tid;
                int r = idx >> 2, c4 = idx & 3;
                const __half* g = Ahi + (size_t)(row0 + r) * lda + k0 + c4 * 8;
                cpasync16(aBase + buf * ABYTES + r * 128 + ((c4 ^ (r & 7)) << 4), g);
            }
        }
#pragma unroll
        for (int i = 0; i < LB; i++) {
            int idx = i * 256 + tid;
            int plane = idx >> 9;
            int ii = idx & 511;
            int k = ii >> 4, c16 = ii & 15;
            const __half* g =
                (plane ? Blo : Bhi) + (size_t)(k0 + k) * ldb + col0 + c16 * 8;
            int c = c16 + plane * 16;
            int p = (c & 24) | ((c ^ k) & 7);
            cpasync16(bBase + buf * BBYTES + k * 512 + (p << 4), g);
        }
    };

    float acc[MT][4][4];
#pragma unroll
    for (int m = 0; m < MT; m++)
#pragma unroll
        for (int n = 0; n < 4; n++)
#pragma unroll
            for (int q = 0; q < 4; q++) acc[m][n][q] = 0.f;

    loadTile(0, 0);
    asm volatile("cp.async.commit_group;\n" ::);
    loadTile(1, 32);
    asm volatile("cp.async.commit_group;\n" ::);
    loadTile(2, 64);
    asm volatile("cp.async.commit_group;\n" ::);

    for (int t = 0; t < nT; t++) {
        asm volatile("cp.async.wait_group 2;\n" ::);
        __syncthreads();
        if (t + 3 < nT) {
            loadTile((t + 3) & 3, (t + 3) * 32);
        }
        asm volatile("cp.async.commit_group;\n" ::);

        const int buf = t & 3;
#pragma unroll
        for (int ks = 0; ks < 2; ks++) {
            unsigned ah[MT][4], al[MT][4], bh[4][2], bl[4][2];
#pragma unroll
            for (int mt = 0; mt < MT; mt++) {
                int rA = wm * MT * 16 + mt * 16 + (lane & 15);
                int ck = ks * 2 + (lane >> 4);
                unsigned base = aBase + buf * ABYTES + rA * 128;
                ldm_x4(base + ((ck ^ (rA & 7)) << 4),
                       ah[mt][0], ah[mt][1], ah[mt][2], ah[mt][3]);
                if (TERMS == 3)
                    ldm_x4(base + (((ck + 4) ^ (rA & 7)) << 4),
                           al[mt][0], al[mt][1], al[mt][2], al[mt][3]);
            }
#pragma unroll
            for (int np = 0; np < 2; np++) {
                int kr = ks * 16 + (lane & 15);
                int cb = wn * 4 + np * 2 + (lane >> 4);
                unsigned base = bBase + buf * BBYTES + kr * 512;
                int ph = (cb & 24) | ((cb ^ kr) & 7);
                ldm_x4t(base + (ph << 4), bh[2 * np][0], bh[2 * np][1],
                        bh[2 * np + 1][0], bh[2 * np + 1][1]);
                if (TERMS == 3) {
                    int cl = cb + 16;
                    int pl = (cl & 24) | ((cl ^ kr) & 7);
                    ldm_x4t(base + (pl << 4), bl[2 * np][0], bl[2 * np][1],
                            bl[2 * np + 1][0], bl[2 * np + 1][1]);
                }
            }
#pragma unroll
            for (int mt = 0; mt < MT; mt++)
#pragma unroll
                for (int nt = 0; nt < 4; nt++) {
                    mma16816(acc[mt][nt], ah[mt], bh[nt]);
                    if (TERMS == 3) {
                        mma16816(acc[mt][nt], al[mt], bh[nt]);
                        mma16816(acc[mt][nt], ah[mt], bl[nt]);
                    }
                }
        }
    }

#pragma unroll
    for (int mt = 0; mt < MT; mt++) {
        int r1 = row0 + wm * MT * 16 + mt * 16 + (lane >> 2);
        int r2 = r1 + 8;
        float s1 = rowScale ? rowScale[rs0 + r1] : 1.f;
        float s2 = rowScale ? rowScale[rs0 + r2] : 1.f;
#pragma unroll
        for (int nt = 0; nt < 4; nt++) {
            int cidx = col0 + wn * 32 + nt * 8 + (lane & 3) * 2;
            float v0 = acc[mt][nt][0] * s1, v1 = acc[mt][nt][1] * s1;
            float v2 = acc[mt][nt][2] * s2, v3 = acc[mt][nt][3] * s2;
            if (act == 1) {
                v0 = fmaxf(v0, 0.f); v1 = fmaxf(v1, 0.f);
                v2 = fmaxf(v2, 0.f); v3 = fmaxf(v3, 0.f);
            }
            if (C) {
                *(float2*)(C + cz + (size_t)r1 * ldc + cidx) = make_float2(v0, v1);
                *(float2*)(C + cz + (size_t)r2 * ldc + cidx) = make_float2(v2, v3);
            }
            if (Chi) {
                __half2 h, l;
                split1(v0, h.x, l.x); split1(v1, h.y, l.y);
                *(__half2*)(Chi + cz + (size_t)r1 * ldc + cidx) = h;
                *(__half2*)(Clo + cz + (size_t)r1 * ldc + cidx) = l;
                split1(v2, h.x, l.x); split1(v3, h.y, l.y);
                *(__half2*)(Chi + cz + (size_t)r2 * ldc + cidx) = h;
                *(__half2*)(Clo + cz + (size_t)r2 * ldc + cidx) = l;
            }
        }
    }
}

// ---------------- split fp32 -> fp16 hi/lo planes ----------------
__global__ void split_k(const float* __restrict__ x, __half* __restrict__ hi,
                        __half* __restrict__ lo, int n) {
    int i = blockIdx.x * 256 + threadIdx.x;
    if (i < n) {
        __half h, l;
        split1(x[i], h, l);
        hi[i] = h; lo[i] = l;
    }
}

// ---------------- s,t from fp32 h: warp per row, 8 rows/block ----------------
__global__ void __launch_bounds__(256) st8_k(
    const float* __restrict__ h, long hStride,
    const float* __restrict__ a, long aStride, int F,
    float* __restrict__ s, float* __restrict__ t,
    unsigned* __restrict__ key) {
    int b = blockIdx.y;
    h += (long)b * hStride;
    a += (long)b * aStride;
    int w = threadIdx.x >> 5, lane = threadIdx.x & 31;
    int row = blockIdx.x * 8 + w;
    const float* hr = h + (size_t)row * F;
    float as = 0.f, at = 0.f;
    for (int k = lane * 4; k < F; k += 128) {
        float4 v = *(const float4*)(hr + k);
        float4 a0 = *(const float4*)(a + k);
        float4 a1 = *(const float4*)(a + F + k);
        as += v.x * a0.x + v.y * a0.y + v.z * a0.z + v.w * a0.w;
        at += v.x * a1.x + v.y * a1.y + v.z * a1.z + v.w * a1.w;
    }
#pragma unroll
    for (int o = 16; o > 0; o >>= 1) {
        as += __shfl_xor_sync(0xffffffffu, as, o);
        at += __shfl_xor_sync(0xffffffffu, at, o);
    }
    if (lane == 0) {
        s[b * NN + row] = as;
        t[b * NN + row] = at;
        atomicMax(&key[b], fenc(at));
    }
}

// ---------------- s,t from fp16 hi/lo planes: warp per row, 8 rows/block ----------------
__global__ void __launch_bounds__(256) st8hl_k(
    const __half* __restrict__ hhi, const __half* __restrict__ hlo,
    long hStride, const float* __restrict__ a, long aStride, int F,
    float* __restrict__ s, float* __restrict__ t,
    unsigned* __restrict__ key) {
    int b = blockIdx.y;
    hhi += (long)b * hStride;
    hlo += (long)b * hStride;
    a += (long)b * aStride;
    int w = threadIdx.x >> 5, lane = threadIdx.x & 31;
    int row = blockIdx.x * 8 + w;
    const __half* hr = hhi + (size_t)row * F;
    const __half* lr = hlo + (size_t)row * F;
    float as = 0.f, at = 0.f;
    for (int k = lane * 8; k < F; k += 256) {
        uint4 hv = *(const uint4*)(hr + k);
        uint4 lv = *(const uint4*)(lr + k);
        const __half* hb = (const __half*)&hv;
        const __half* lb = (const __half*)&lv;
#pragma unroll
        for (int q = 0; q < 8; q++) {
            float v = __half2float(hb[q]) + __half2float(lb[q]);
            as += v * a[k + q];
            at += v * a[F + k + q];
        }
    }
#pragma unroll
    for (int o = 16; o > 0; o >>= 1) {
        as += __shfl_xor_sync(0xffffffffu, as, o);
        at += __shfl_xor_sync(0xffffffffu, at, o);
    }
    if (lane == 0) {
        s[b * NN + row] = as;
        t[b * NN + row] = at;
        atomicMax(&key[b], fenc(at));
    }
}

__global__ void etf_k(const float* __restrict__ t, const unsigned* __restrict__ key,
                      float* __restrict__ maxt, float* __restrict__ E,
                      float* __restrict__ Fv) {
    int b = blockIdx.y;
    float mt = fdec(key[b]);
    if (blockIdx.x == 0 && threadIdx.x == 0) maxt[b] = mt;
    int j = blockIdx.x * 512 + threadIdx.x;
    float tv = t[b * NN + j] - mt;
    E[b * NN + j] = expf(tv);
    Fv[b * NN + j] = expf(0.2f * tv);
}

// ---------------- per-row masked softmax weights -> single fp16 plane, z-batched ----
__global__ void __launch_bounds__(256) attn8_k(
    const float* __restrict__ s, const float* __restrict__ E,
    const float* __restrict__ Fv, const float* __restrict__ maxt,
    const unsigned* __restrict__ mask,
    __half* __restrict__ Pf, float* __restrict__ invZ) {
    __shared__ float shE[NN];
    __shared__ float shF[NN];
    const int z = blockIdx.y;
    s += (size_t)z * NN;
    E += (size_t)z * NN;
    Fv += (size_t)z * NN;
    Pf += (size_t)z * NN * NN;
    invZ += (size_t)z * NN;

    int tid = threadIdx.x;
#pragma unroll
    for (int j = 0; j < 4; j++) {
        ((float4*)shE)[j * 256 + tid] = ((const float4*)E)[j * 256 + tid];
        ((float4*)shF)[j * 256 + tid] = ((const float4*)Fv)[j * 256 + tid];
    }
    __syncthreads();

    const int w = tid >> 5, lane = tid & 31;
    const int row = blockIdx.x * 8 + w;
    float q = s[row] + maxt[z];
    float m = fmaxf(q, 0.2f * q);
    float c = expf(q - m);
    float d = expf(0.2f * q - m);

    const unsigned* mrow = mask + (size_t)row * 128;
    __half* PRow = Pf + (size_t)row * NN;

    float sum = 0.f;
#pragma unroll
    for (int it = 0; it < 16; it++) {
        int j0 = it * 256 + lane * 8;
        unsigned mbyte = (mrow[j0 >> 5] >> (j0 & 31)) & 0xFFu;
        float4 e0 = ((const float4*)shE)[j0 >> 2];
        float4 e1 = ((const float4*)shE)[(j0 >> 2) + 1];
        float4 f0 = ((const float4*)shF)[j0 >> 2];
        float4 f1 = ((const float4*)shF)[(j0 >> 2) + 1];
        float e[8] = {e0.x, e0.y, e0.z, e0.w, e1.x, e1.y, e1.z, e1.w};
        float f[8] = {f0.x, f0.y, f0.z, f0.w, f1.x, f1.y, f1.z, f1.w};
        __half pb[8];
#pragma unroll
        for (int k = 0; k < 8; k++) {
            float p = ((mbyte >> k) & 1u) ? fmaxf(c * e[k], d * f[k]) : 0.f;
            sum += p;
            pb[k] = __float2half(p);
        }
        *(uint4*)(PRow + j0) = *(const uint4*)pb;
    }
#pragma unroll
    for (int o = 16; o > 0; o >>= 1) sum += __shfl_xor_sync(0xffffffffu, sum, o);
    if (lane == 0) invZ[row] = 1.f / sum;
}

// ---------------- GroupNorm ----------------
__global__ void gn_reduce1_k(const float* __restrict__ h, float* __restrict__ part) {
    __shared__ float r1[256], r2[256];
    int tid = threadIdx.x;
    float s = 0.f, q = 0.f;
    for (size_t idx = (size_t)blockIdx.x * 256 + tid; idx < (size_t)NN * 1536;
         idx += (size_t)2048 * 256) {
        float v = h[idx];
        s += v;
        q += v * v;
    }
    r1[tid] = s; r2[tid] = q;
    __syncthreads();
    for (int s2 = 128; s2 > 0; s2 >>= 1) {
        if (tid < s2) { r1[tid] += r1[tid + s2]; r2[tid] += r2[tid + s2]; }
        __syncthreads();
    }
    if (tid == 0) { part[blockIdx.x] = r1[0]; part[2048 + blockIdx.x] = r2[0]; }
}

__global__ void gn_reduce2_k(const float* __restrict__ part, float* __restrict__ stats) {
    __shared__ double r1[1024], r2[1024];
    int tid = threadIdx.x;
    double s = 0.0, q = 0.0;
    for (int i = tid; i < 2048; i += 1024) { s += part[i]; q += part[2048 + i]; }
    r1[tid] = s; r2[tid] = q;
    __syncthreads();
    for (int s2 = 512; s2 > 0; s2 >>= 1) {
        if (tid < s2) { r1[tid] += r1[tid + s2]; r2[tid] += r2[tid + s2]; }
        __syncthreads();
    }
    if (tid == 0) {
        double n = (double)NN * 1536.0;
        double mu = r1[0] / n;
        double var = (r2[0] - n * mu * mu) / (n - 1.0);
        stats[0] = (float)mu;
        stats[1] = (float)(1.0 / sqrt(var + 1e-5));
    }
}

__global__ void gn_apply_k(const float* __restrict__ h, const float* __restrict__ w,
                           const float* __restrict__ b, const float* __restrict__ stats,
                           __half* __restrict__ hi, __half* __restrict__ lo) {
    size_t idx = (size_t)blockIdx.x * 256 + threadIdx.x;
    if (idx < (size_t)NN * 1536) {
        int c = (int)(idx % 1536);
        float v = (h[idx] - stats[0]) * stats[1] * w[c] + b[c];
        __half hh, ll;
        split1(v, hh, ll);
        hi[idx] = hh; lo[idx] = ll;
    }
}

// ---------------- host ----------------
extern "C" void kernel_launch(void* const* d_in, const int* in_sizes, int n_in,
                              void* d_out, int out_size) {
    const float* x       = (const float*)d_in[0];
    const int*   adj     = (const int*)d_in[1];
    const float* lin1_w  = (const float*)d_in[2];
    const float* lin1_b  = (const float*)d_in[3];
    const float* lin2_w  = (const float*)d_in[4];
    const float* lin2_b  = (const float*)d_in[5];
    const float* conv1_W = (const float*)d_in[6];
    const float* conv1_a = (const float*)d_in[7];
    const float* att_W   = (const float*)d_in[8];
    const float* att_a   = (const float*)d_in[9];
    const float* gn_w    = (const float*)d_in[10];
    const float* gn_b    = (const float*)d_in[11];
    const float* conv2_W = (const float*)d_in[12];
    const float* conv2_a = (const float*)d_in[13];
    float* out = (float*)d_out;

    void* p;
    cudaGetSymbolAddress(&p, g_Pf);     __half* Pf = (__half*)p;
    cudaGetSymbolAddress(&p, g_hA);     float* hA = (float*)p;
    cudaGetSymbolAddress(&p, g_hAhi);   __half* hAhi = (__half*)p;
    cudaGetSymbolAddress(&p, g_hAlo);   __half* hAlo = (__half*)p;
    cudaGetSymbolAddress(&p, g_out1hi); __half* out1hi = (__half*)p;
    cudaGetSymbolAddress(&p, g_out1lo); __half* out1lo = (__half*)p;
    cudaGetSymbolAddress(&p, g_cat);    float* cat = (float*)p;
    cudaGetSymbolAddress(&p, g_cathi);  __half* cathi = (__half*)p;
    cudaGetSymbolAddress(&p, g_catlo);  __half* catlo = (__half*)p;
    cudaGetSymbolAddress(&p, g_hB6hi);  __half* hB6hi = (__half*)p;
    cudaGetSymbolAddress(&p, g_hB6lo);  __half* hB6lo = (__half*)p;
    cudaGetSymbolAddress(&p, g_hBhi);   __half* hBhi = (__half*)p;
    cudaGetSymbolAddress(&p, g_hBlo);   __half* hBlo = (__half*)p;
    cudaGetSymbolAddress(&p, g_attWhi); __half* attWhi = (__half*)p;
    cudaGetSymbolAddress(&p, g_attWlo); __half* attWlo = (__half*)p;
    cudaGetSymbolAddress(&p, g_c2Whi);  __half* c2Whi = (__half*)p;
    cudaGetSymbolAddress(&p, g_c2Wlo);  __half* c2Wlo = (__half*)p;
    cudaGetSymbolAddress(&p, g_l1);     float* l1 = (float*)p;
    cudaGetSymbolAddress(&p, g_l2);     float* l2 = (float*)p;
    cudaGetSymbolAddress(&p, g_sv);     float* sv = (float*)p;
    cudaGetSymbolAddress(&p, g_tv);     float* tv = (float*)p;
    cudaGetSymbolAddress(&p, g_E);      float* E = (float*)p;
    cudaGetSymbolAddress(&p, g_Fv);     float* Fv = (float*)p;
    cudaGetSymbolAddress(&p, g_maxtKey);unsigned* keys = (unsigned*)p;
    cudaGetSymbolAddress(&p, g_maxt);   float* maxt = (float*)p;
    cudaGetSymbolAddress(&p, g_invZ);   float* invZ = (float*)p;
    cudaGetSymbolAddress(&p, g_mask);   unsigned* mask = (unsigned*)p;
    cudaGetSymbolAddress(&p, g_part);   float* part = (float*)p;
    cudaGetSymbolAddress(&p, g_stats);  float* stats = (float*)p;

    cudaFuncSetAttribute(mma3_k<2, 1>, cudaFuncAttributeMaxDynamicSharedMemorySize, 98304);
    cudaFuncSetAttribute(mma3_k<2, 3>, cudaFuncAttributeMaxDynamicSharedMemorySize, 98304);

    pack_mask_k<<<NN, 128>>>(adj, mask, keys);

    // lin1 + lin2 + conv1 projection (fp32)
    gemm128_k<64, 4><<<dim3(1, 32), 256>>>(x,  lin1_w, l1, 128, 128, 64, 64, lin1_b, 0);
    gemm128_k<64, 4><<<dim3(1, 32), 256>>>(l1, lin2_w, l2, 64, 64, 64, 64, lin2_b, 0);
    gemm128_k<128, 8><<<dim3(4, 32), 256>>>(l2, conv1_W, hA, 64, 64, 512, 512, nullptr, 0);
    split_k<<<(NN * 512 + 255) / 256, 256>>>(hA, hAhi, hAlo, NN * 512);

    split_k<<<(6 * 512 * 256 + 255) / 256, 256>>>(att_W, attWhi, attWlo, 6 * 512 * 256);
    split_k<<<(1536 * 256 + 255) / 256, 256>>>(conv2_W, c2Whi, c2Wlo, 1536 * 256);

    // ---- GAT conv1 (F=512): P slot 0, invZ slot 0 ----
    st8_k<<<dim3(512, 1), 256>>>(hA, 0, conv1_a, 0, 512, sv, tv, keys);
    etf_k<<<dim3(8, 1), 512>>>(tv, keys, maxt, E, Fv);
    attn8_k<<<dim3(512, 1), 256>>>(sv, E, Fv, maxt, mask, Pf, invZ);
    mma3_k<2, 1><<<dim3(4, 64, 1), 256, 98304>>>(Pf, nullptr, hAhi, nullptr,
                                                 nullptr, out1hi, out1lo,
                                                 NN, NN, 512, 512, invZ, 1,
                                                 0, 0, 0, 0);

    // ---- 6 head projections, batched (fp16 planes) ----
    mma3_k<2, 3><<<dim3(2, 64, 6), 256, 98304>>>(out1hi, out1lo, attWhi, attWlo,
                                                 nullptr, hB6hi, hB6lo,
                                                 512, 512, 256, 256, nullptr, 0,
                                                 0, (long)512 * 256, (long)NN * 256, 0);
    st8hl_k<<<dim3(512, 6), 256>>>(hB6hi, hB6lo, (long)NN * 256, att_a, 512, 256,
                                   sv + NN, tv + NN, keys + 1);
    etf_k<<<dim3(8, 6), 512>>>(tv + NN, keys + 1, maxt + 1, E + NN, Fv + NN);
    attn8_k<<<dim3(512, 6), 256>>>(sv + NN, E + NN, Fv + NN, maxt + 1, mask, Pf, invZ);
    mma3_k<2, 1><<<dim3(2, 64, 6), 256, 98304>>>(Pf, nullptr, hB6hi, nullptr,
                                                 cat, nullptr, nullptr,
                                                 NN, NN, 256, 1536, invZ, 1,
                                                 (long)NN * NN, (long)NN * 256, 256, NN);

    // ---- GroupNorm ----
    gn_reduce1_k<<<2048, 256>>>(cat, part);
    gn_reduce2_k<<<1, 1024>>>(part, stats);
    gn_apply_k<<<(int)(((size_t)NN * 1536 + 255) / 256), 256>>>(cat, gn_w, gn_b, stats,
                                                                cathi, catlo);

    // ---- GAT conv2 (F=256): P slot 0, invZ slot 0, data slot 7 ----
    mma3_k<2, 3><<<dim3(2, 64, 1), 256, 98304>>>(cathi, catlo, c2Whi, c2Wlo,
                                                 nullptr, hBhi, hBlo,
                                                 1536, 1536, 256, 256, nullptr, 0,
                                                 0, 0, 0, 0);
    st8hl_k<<<dim3(512, 1), 256>>>(hBhi, hBlo, 0, conv2_a, 0, 256,
                                   sv + 7 * NN, tv + 7 * NN, keys + 7);
    etf_k<<<dim3(8, 1), 512>>>(tv + 7 * NN, keys + 7, maxt + 7, E + 7 * NN, Fv + 7 * NN);
    attn8_k<<<dim3(512, 1), 256>>>(sv + 7 * NN, E + 7 * NN, Fv + 7 * NN, maxt + 7, mask,
                                   Pf, invZ);
    mma3_k<2, 1><<<dim3(2, 64, 1), 256, 98304>>>(Pf, nullptr, hBhi, nullptr,
                                                 out, nullptr, nullptr,
                                                 NN, NN, 256, 256, invZ, 0,
                                                 0, 0, 0, 0);
}